// round 1
// baseline (speedup 1.0000x reference)
#include <cuda_runtime.h>
#include <math.h>

// ---------------- problem constants ----------------
#define Bsz   4
#define Lsz   2048
#define Dsz   2048
#define NHs   16
#define DHs   128
#define DHRs  64
#define DCs   1024
#define DTOT  (DHs + DHRs)     // 192
#define Msz   (Bsz * Lsz)      // 8192

// ---------------- scratch (device globals; no allocs allowed) ----------------
__device__ float g_ckv[Msz * DCs];            // x @ W_DKV
__device__ float g_cq [Msz * DCs];            // x @ W_DQ
__device__ float g_kc [Msz * Dsz];            // c_kv @ W_UK
__device__ float g_vt [Msz * Dsz];            // c_kv @ W_UV
__device__ float g_qc [Msz * Dsz];            // c_q @ W_UQ
__device__ float g_qr [Msz * (NHs * DHRs)];   // c_q @ W_QR
__device__ float g_kr [Msz * DHRs];           // x @ W_KR
__device__ float g_Q  [Bsz * NHs * Lsz * DTOT];
__device__ float g_K  [Bsz * NHs * Lsz * DTOT];
__device__ float g_V  [Bsz * NHs * Lsz * DHs];
__device__ float g_ao [Msz * Dsz];            // attention output (B,L,D)

// ---------------- generic fp32 SGEMM: C[M,N] = A[M,K] @ B[K,N] ----------------
// 128x128 block tile, BK=8, 256 threads, 8x8 per thread.
__global__ void __launch_bounds__(256)
sgemm_kernel(const float* __restrict__ A, const float* __restrict__ B,
             float* __restrict__ C, int M, int N, int K) {
    __shared__ float As[8][128];
    __shared__ float Bs[8][128];

    const int tid = threadIdx.x;
    const int tx = tid & 15;          // 0..15  -> n micro
    const int ty = tid >> 4;          // 0..15  -> m micro
    const int m0 = blockIdx.y * 128;
    const int n0 = blockIdx.x * 128;

    // A load mapping: 128 rows x 8 cols = 256 float4
    const int arow = tid >> 1;            // 0..127
    const int acg  = (tid & 1) * 4;       // 0 or 4
    // B load mapping: 8 rows x 128 cols = 256 float4
    const int brow = tid >> 5;            // 0..7
    const int bcol = (tid & 31) * 4;      // 0..124

    float acc[8][8];
#pragma unroll
    for (int i = 0; i < 8; ++i)
#pragma unroll
        for (int j = 0; j < 8; ++j) acc[i][j] = 0.f;

    for (int k0 = 0; k0 < K; k0 += 8) {
        // load A tile (M,K row-major); M,K assumed multiples of tile in our uses
        {
            float4 av = *(const float4*)&A[(size_t)(m0 + arow) * K + k0 + acg];
            As[acg + 0][arow] = av.x;
            As[acg + 1][arow] = av.y;
            As[acg + 2][arow] = av.z;
            As[acg + 3][arow] = av.w;
        }
        // load B tile (K,N row-major) with N guard
        {
            float4 bv = make_float4(0.f, 0.f, 0.f, 0.f);
            int col = n0 + bcol;
            if (col + 3 < N) {
                bv = *(const float4*)&B[(size_t)(k0 + brow) * N + col];
            } else {
                const float* bp = &B[(size_t)(k0 + brow) * N];
                if (col + 0 < N) bv.x = bp[col + 0];
                if (col + 1 < N) bv.y = bp[col + 1];
                if (col + 2 < N) bv.z = bp[col + 2];
                if (col + 3 < N) bv.w = bp[col + 3];
            }
            Bs[brow][bcol + 0] = bv.x;
            Bs[brow][bcol + 1] = bv.y;
            Bs[brow][bcol + 2] = bv.z;
            Bs[brow][bcol + 3] = bv.w;
        }
        __syncthreads();

#pragma unroll
        for (int kk = 0; kk < 8; ++kk) {
            float a[8], bb[8];
            float4 a0 = *(const float4*)&As[kk][ty * 8];
            float4 a1 = *(const float4*)&As[kk][ty * 8 + 4];
            float4 b0 = *(const float4*)&Bs[kk][tx * 8];
            float4 b1 = *(const float4*)&Bs[kk][tx * 8 + 4];
            a[0]=a0.x; a[1]=a0.y; a[2]=a0.z; a[3]=a0.w;
            a[4]=a1.x; a[5]=a1.y; a[6]=a1.z; a[7]=a1.w;
            bb[0]=b0.x; bb[1]=b0.y; bb[2]=b0.z; bb[3]=b0.w;
            bb[4]=b1.x; bb[5]=b1.y; bb[6]=b1.z; bb[7]=b1.w;
#pragma unroll
            for (int i = 0; i < 8; ++i)
#pragma unroll
                for (int j = 0; j < 8; ++j)
                    acc[i][j] = fmaf(a[i], bb[j], acc[i][j]);
        }
        __syncthreads();
    }

#pragma unroll
    for (int i = 0; i < 8; ++i) {
        int row = m0 + ty * 8 + i;
        if (row >= M) continue;
#pragma unroll
        for (int j = 0; j < 8; ++j) {
            int col = n0 + tx * 8 + j;
            if (col < N) C[(size_t)row * N + col] = acc[i][j];
        }
    }
}

// ---------------- assemble: RoPE + concat + L2-normalize + transpose ----------------
// One block per (b,l), 512 threads = 16 warps, warp w = head w.
#define LOG2_ROPE_BASE 13.287712379549449f   // log2(10000)

__global__ void __launch_bounds__(512)
assemble_kernel(const float* __restrict__ s_qk_ptr) {
    const int bl = blockIdx.x;            // b*L + l
    const int b  = bl / Lsz;
    const int l  = bl % Lsz;
    const int w    = threadIdx.x >> 5;    // head
    const int lane = threadIdx.x & 31;
    const float s_qk = *s_qk_ptr;

    float qv[6], kv[6];
    float ssq = 0.f, ssk = 0.f;

#pragma unroll
    for (int j = 0; j < 6; ++j) {
        int d = j * 32 + lane;
        float qx, kx;
        if (d < DHs) {
            qx = g_qc[(size_t)bl * Dsz + w * DHs + d];
            kx = g_kc[(size_t)bl * Dsz + w * DHs + d];
        } else {
            int dr = d - DHs;               // 0..63
            int i  = dr & 31;
            float invf = exp2f(-(float)i * (LOG2_ROPE_BASE / 32.0f));
            float ang  = (float)l * invf;
            float sn, cs;
            sincosf(ang, &sn, &cs);
            const float* qrp = &g_qr[(size_t)bl * (NHs * DHRs) + w * DHRs];
            float x1 = qrp[dr];
            float x2 = (dr < 32) ? -qrp[dr + 32] : qrp[dr - 32];
            qx = x1 * cs + x2 * sn;
            const float* krp = &g_kr[(size_t)bl * DHRs];
            float y1 = krp[dr];
            float y2 = (dr < 32) ? -krp[dr + 32] : krp[dr - 32];
            kx = y1 * cs + y2 * sn;
        }
        qv[j] = qx; kv[j] = kx;
        ssq += qx * qx; ssk += kx * kx;
    }
#pragma unroll
    for (int o = 16; o; o >>= 1) {
        ssq += __shfl_xor_sync(0xffffffffu, ssq, o);
        ssk += __shfl_xor_sync(0xffffffffu, ssk, o);
    }
    float qn = s_qk / fmaxf(sqrtf(ssq), 1e-12f);
    float kn = 1.0f / fmaxf(sqrtf(ssk), 1e-12f);

    size_t base = ((size_t)(b * NHs + w) * Lsz + l);
#pragma unroll
    for (int j = 0; j < 6; ++j) {
        int d = j * 32 + lane;
        g_Q[base * DTOT + d] = qv[j] * qn;
        g_K[base * DTOT + d] = kv[j] * kn;
    }
#pragma unroll
    for (int dd = 0; dd < 4; ++dd) {
        int d = dd * 32 + lane;
        g_V[base * DHs + d] = g_vt[(size_t)bl * Dsz + w * DHs + d];
    }
}

// ---------------- causal flash attention, fp32, 64x64 tiles ----------------
#define FBQ 64
#define FBK 64
#define SQ  193   // padded row stride for Q/K tiles (kills bank conflicts)
#define FLASH_SMEM_BYTES ((FBQ*SQ + FBK*SQ + FBK*DHs + FBQ*FBK) * sizeof(float))

__global__ void __launch_bounds__(256)
flash_kernel() {
    extern __shared__ float sm[];
    float* Qs = sm;                       // FBQ * SQ
    float* Ks = Qs + FBQ * SQ;            // FBK * SQ
    float* Vs = Ks + FBK * SQ;            // FBK * DHs
    float* Ps = Vs + FBK * DHs;           // FBQ * FBK

    const int qt = blockIdx.x;
    const int h  = blockIdx.y;
    const int b  = blockIdx.z;
    const int tid  = threadIdx.x;
    const int w    = tid >> 5;            // warp -> 8 q rows
    const int lane = tid & 31;
    const int q0 = qt * FBQ;

    const float* Qg  = g_Q + ((size_t)(b * NHs + h) * Lsz + q0) * DTOT;
    const float* Kg0 = g_K + (size_t)(b * NHs + h) * Lsz * DTOT;
    const float* Vg0 = g_V + (size_t)(b * NHs + h) * Lsz * DHs;

    for (int idx = tid; idx < FBQ * DTOT; idx += 256)
        Qs[(idx / DTOT) * SQ + (idx % DTOT)] = Qg[idx];

    float m[8], lsum[8], acc[8][4];
#pragma unroll
    for (int r = 0; r < 8; ++r) {
        m[r] = -1e30f; lsum[r] = 0.f;
#pragma unroll
        for (int dd = 0; dd < 4; ++dd) acc[r][dd] = 0.f;
    }

    for (int kt = 0; kt <= qt; ++kt) {
        __syncthreads();
        const int k0 = kt * FBK;
        for (int idx = tid; idx < FBK * DTOT; idx += 256)
            Ks[(idx / DTOT) * SQ + (idx % DTOT)] = Kg0[(size_t)k0 * DTOT + idx];
        for (int idx = tid; idx < FBK * DHs; idx += 256)
            Vs[idx] = Vg0[(size_t)k0 * DHs + idx];
        __syncthreads();

        const bool diag = (kt == qt);
        const int c0 = lane, c1 = lane + 32;

#pragma unroll
        for (int r = 0; r < 8; ++r) {
            const int row = w * 8 + r;
            const float* qp  = Qs + row * SQ;
            const float* kp0 = Ks + c0 * SQ;
            const float* kp1 = Ks + c1 * SQ;
            float s0 = 0.f, s1 = 0.f;
#pragma unroll 8
            for (int k = 0; k < DTOT; ++k) {
                float qvv = qp[k];
                s0 = fmaf(qvv, kp0[k], s0);
                s1 = fmaf(qvv, kp1[k], s1);
            }
            if (diag) {
                int rg = q0 + row;
                if (k0 + c0 > rg) s0 = -1e30f;
                if (k0 + c1 > rg) s1 = -1e30f;
            }
            float mt = fmaxf(s0, s1);
#pragma unroll
            for (int o = 16; o; o >>= 1)
                mt = fmaxf(mt, __shfl_xor_sync(0xffffffffu, mt, o));
            float mnew = fmaxf(m[r], mt);
            float p0 = expf(s0 - mnew);
            float p1 = expf(s1 - mnew);
            float rs = p0 + p1;
#pragma unroll
            for (int o = 16; o; o >>= 1)
                rs += __shfl_xor_sync(0xffffffffu, rs, o);
            float scale = expf(m[r] - mnew);
            m[r] = mnew;
            lsum[r] = lsum[r] * scale + rs;
#pragma unroll
            for (int dd = 0; dd < 4; ++dd) acc[r][dd] *= scale;
            Ps[row * FBK + c0] = p0;
            Ps[row * FBK + c1] = p1;
        }
        __syncwarp();

        // acc += P @ V   (each lane owns cols lane+32*dd of its warp's 8 rows)
#pragma unroll 4
        for (int c = 0; c < FBK; ++c) {
            float v0 = Vs[c * DHs +  0 + lane];
            float v1 = Vs[c * DHs + 32 + lane];
            float v2 = Vs[c * DHs + 64 + lane];
            float v3 = Vs[c * DHs + 96 + lane];
            const float* pr = Ps + (w * 8) * FBK + c;
#pragma unroll
            for (int r = 0; r < 8; ++r) {
                float p = pr[r * FBK];
                acc[r][0] = fmaf(p, v0, acc[r][0]);
                acc[r][1] = fmaf(p, v1, acc[r][1]);
                acc[r][2] = fmaf(p, v2, acc[r][2]);
                acc[r][3] = fmaf(p, v3, acc[r][3]);
            }
        }
    }

#pragma unroll
    for (int r = 0; r < 8; ++r) {
        float inv = 1.0f / lsum[r];
        int row = q0 + w * 8 + r;
        size_t ob = ((size_t)(b * Lsz + row)) * Dsz + h * DHs;
#pragma unroll
        for (int dd = 0; dd < 4; ++dd)
            g_ao[ob + dd * 32 + lane] = acc[r][dd] * inv;
    }
}

// ---------------- launcher ----------------
extern "C" void kernel_launch(void* const* d_in, const int* in_sizes, int n_in,
                              void* d_out, int out_size) {
    const float* x     = (const float*)d_in[0];
    const float* W_DKV = (const float*)d_in[1];
    const float* W_UK  = (const float*)d_in[2];
    const float* W_UV  = (const float*)d_in[3];
    const float* W_DQ  = (const float*)d_in[4];
    const float* W_UQ  = (const float*)d_in[5];
    const float* W_QR  = (const float*)d_in[6];
    const float* W_KR  = (const float*)d_in[7];
    const float* W_O   = (const float*)d_in[8];
    const float* s_qk  = (const float*)d_in[9];
    float* out = (float*)d_out;

    float *ckv, *cq, *kc, *vt, *qc, *qr, *kr, *ao;
    cudaGetSymbolAddress((void**)&ckv, g_ckv);
    cudaGetSymbolAddress((void**)&cq,  g_cq);
    cudaGetSymbolAddress((void**)&kc,  g_kc);
    cudaGetSymbolAddress((void**)&vt,  g_vt);
    cudaGetSymbolAddress((void**)&qc,  g_qc);
    cudaGetSymbolAddress((void**)&qr,  g_qr);
    cudaGetSymbolAddress((void**)&kr,  g_kr);
    cudaGetSymbolAddress((void**)&ao,  g_ao);

    dim3 blk(256);
    const int MT = Msz / 128;  // 64

    // down-projections + k_rope from x
    sgemm_kernel<<<dim3(DCs / 128, MT), blk>>>(x, W_DKV, ckv, Msz, DCs, Dsz);
    sgemm_kernel<<<dim3(DCs / 128, MT), blk>>>(x, W_DQ,  cq,  Msz, DCs, Dsz);
    sgemm_kernel<<<dim3(1,         MT), blk>>>(x, W_KR,  kr,  Msz, DHRs, Dsz);

    // up-projections
    sgemm_kernel<<<dim3(Dsz / 128, MT), blk>>>(ckv, W_UK, kc, Msz, Dsz, DCs);
    sgemm_kernel<<<dim3(Dsz / 128, MT), blk>>>(ckv, W_UV, vt, Msz, Dsz, DCs);
    sgemm_kernel<<<dim3(Dsz / 128, MT), blk>>>(cq,  W_UQ, qc, Msz, Dsz, DCs);
    sgemm_kernel<<<dim3((NHs * DHRs) / 128, MT), blk>>>(cq, W_QR, qr, Msz, NHs * DHRs, DCs);

    // RoPE + concat + normalize + transpose
    assemble_kernel<<<Msz, 512>>>(s_qk);

    // causal flash attention
    cudaFuncSetAttribute(flash_kernel, cudaFuncAttributeMaxDynamicSharedMemorySize,
                         (int)FLASH_SMEM_BYTES);
    flash_kernel<<<dim3(Lsz / FBQ, NHs, Bsz), 256, FLASH_SMEM_BYTES>>>();

    // output projection
    sgemm_kernel<<<dim3(Dsz / 128, MT), blk>>>(ao, W_O, out, Msz, Dsz, Dsz);
}

// round 4
// speedup vs baseline: 1.4291x; 1.4291x over previous
#include <cuda_runtime.h>
#include <cuda_bf16.h>
#include <math.h>
#include <stdint.h>

// ---------------- problem constants ----------------
#define Bsz   4
#define Lsz   2048
#define Dsz   2048
#define NHs   16
#define DHs   128
#define DHRs  64
#define DCs   1024
#define DTOT  (DHs + DHRs)     // 192
#define Msz   (Bsz * Lsz)      // 8192

// ---------------- fp32 scratch ----------------
__device__ float g_ckv[Msz * DCs];
__device__ float g_cq [Msz * DCs];
__device__ float g_kc [Msz * Dsz];
__device__ float g_vt [Msz * Dsz];
__device__ float g_qc [Msz * Dsz];
__device__ float g_qr [Msz * (NHs * DHRs)];
__device__ float g_kr [Msz * DHRs];
__device__ float g_Q  [Bsz * NHs * Lsz * DTOT];
__device__ float g_K  [Bsz * NHs * Lsz * DTOT];
__device__ float g_V  [Bsz * NHs * Lsz * DHs];
__device__ float g_ao [Msz * Dsz];

// ---------------- bf16 split scratch ----------------
__device__ __align__(256) __nv_bfloat16 g_xh [Msz * Dsz];
__device__ __align__(256) __nv_bfloat16 g_xl [Msz * Dsz];
__device__ __align__(256) __nv_bfloat16 g_ckvh[Msz * DCs];
__device__ __align__(256) __nv_bfloat16 g_ckvl[Msz * DCs];
__device__ __align__(256) __nv_bfloat16 g_cqh [Msz * DCs];
__device__ __align__(256) __nv_bfloat16 g_cql [Msz * DCs];
__device__ __align__(256) __nv_bfloat16 g_aoh [Msz * Dsz];
__device__ __align__(256) __nv_bfloat16 g_aol [Msz * Dsz];
// transposed weights [N x K], hi/lo
__device__ __align__(256) __nv_bfloat16 g_wdkvh[DCs * Dsz], g_wdkvl[DCs * Dsz];
__device__ __align__(256) __nv_bfloat16 g_wdqh [DCs * Dsz], g_wdql [DCs * Dsz];
__device__ __align__(256) __nv_bfloat16 g_wukh [Dsz * DCs], g_wukl [Dsz * DCs];
__device__ __align__(256) __nv_bfloat16 g_wuvh [Dsz * DCs], g_wuvl [Dsz * DCs];
__device__ __align__(256) __nv_bfloat16 g_wuqh [Dsz * DCs], g_wuql [Dsz * DCs];
__device__ __align__(256) __nv_bfloat16 g_wqrh [(NHs*DHRs) * DCs], g_wqrl[(NHs*DHRs) * DCs];
__device__ __align__(256) __nv_bfloat16 g_woh  [Dsz * Dsz], g_wol  [Dsz * Dsz];

// ---------------- PTX helpers (baseline ISA only; no sm_103a features) ----------------
__device__ __forceinline__ uint32_t smem_u32(const void* p) {
    uint32_t a;
    asm("{ .reg .u64 t; cvta.to.shared.u64 t, %1; cvt.u32.u64 %0, t; }" : "=r"(a) : "l"(p));
    return a;
}
__device__ __forceinline__ void cpa16(uint32_t s, const void* g) {
    asm volatile("cp.async.cg.shared.global [%0], [%1], 16;" :: "r"(s), "l"(g) : "memory");
}
__device__ __forceinline__ void cp_commit() {
    asm volatile("cp.async.commit_group;" ::: "memory");
}
template <int N> __device__ __forceinline__ void cp_wait_group() {
    asm volatile("cp.async.wait_group %0;" :: "n"(N) : "memory");
}
__device__ __forceinline__ void ldm_x4(uint32_t* r, uint32_t addr) {
    asm volatile("ldmatrix.sync.aligned.m8n8.x4.shared.b16 {%0,%1,%2,%3}, [%4];"
                 : "=r"(r[0]), "=r"(r[1]), "=r"(r[2]), "=r"(r[3]) : "r"(addr));
}
__device__ __forceinline__ void mma_bf16(float* c, const uint32_t* a, const uint32_t* b) {
    asm volatile(
        "mma.sync.aligned.m16n8k16.row.col.f32.bf16.bf16.f32 "
        "{%0,%1,%2,%3}, {%4,%5,%6,%7}, {%8,%9}, {%0,%1,%2,%3};"
        : "+f"(c[0]), "+f"(c[1]), "+f"(c[2]), "+f"(c[3])
        : "r"(a[0]), "r"(a[1]), "r"(a[2]), "r"(a[3]), "r"(b[0]), "r"(b[1]));
}

// ---------------- split / transpose-split conversions ----------------
__global__ void split_kernel(const float* __restrict__ src,
                             __nv_bfloat16* __restrict__ hi,
                             __nv_bfloat16* __restrict__ lo, int n) {
    int i = blockIdx.x * 256 + threadIdx.x;
    if (i < n) {
        float x = src[i];
        __nv_bfloat16 h = __float2bfloat16(x);
        float r = x - __bfloat162float(h);
        hi[i] = h;
        lo[i] = __float2bfloat16(r);
    }
}

// W[K x N] row-major -> Th/Tl [N x K] row-major bf16 hi/lo
__global__ void tsplit_kernel(const float* __restrict__ W,
                              __nv_bfloat16* __restrict__ Th,
                              __nv_bfloat16* __restrict__ Tl, int K, int N) {
    __shared__ float t[32][33];
    int kb = blockIdx.y * 32, nb = blockIdx.x * 32;
    int tx = threadIdx.x, ty = threadIdx.y;    // (32, 8)
#pragma unroll
    for (int r = 0; r < 32; r += 8)
        t[ty + r][tx] = W[(size_t)(kb + ty + r) * N + nb + tx];
    __syncthreads();
#pragma unroll
    for (int r = 0; r < 32; r += 8) {
        float x = t[tx][ty + r];
        __nv_bfloat16 h = __float2bfloat16(x);
        float res = x - __bfloat162float(h);
        size_t o = (size_t)(nb + ty + r) * K + kb + tx;
        Th[o] = h;
        Tl[o] = __float2bfloat16(res);
    }
}

// ---------------- mma.sync bf16 split-3 GEMM ----------------
// C[M,N] = A[M,K] @ Bt[N,K]^T with A,Bt as bf16 hi/lo (K-major).
// 128x128x32 tile, 256 threads (8 warps, warp tile 32x64), 2-stage cp.async.
// Smem per stage: Ah,Al,Bh,Bl each 128 rows x 64B = 8KB -> 32KB; 2 stages = 64KB.
#define MMS_A_H 0
#define MMS_A_L 8192
#define MMS_B_H 16384
#define MMS_B_L 24576
#define MMS_STAGE 32768
#define MM_SMEM (2 * MMS_STAGE)

__device__ __forceinline__ void mm_load_stage(
    uint32_t sbase,
    const __nv_bfloat16* __restrict__ Ah, const __nv_bfloat16* __restrict__ Al,
    const __nv_bfloat16* __restrict__ Bh, const __nv_bfloat16* __restrict__ Bl,
    int m0, int n0, int k0, int Kd, int tid)
{
#pragma unroll
    for (int t = 0; t < 2; ++t) {
        int idx = tid + t * 256;            // 0..511
        int row = idx >> 2;                 // 0..127
        int c   = idx & 3;                  // 16B chunk within 64B row
        uint32_t so = (uint32_t)(row * 64 + ((c ^ (row & 3)) << 4));
        size_t ga = (size_t)(m0 + row) * Kd + k0 + c * 8;
        size_t gb = (size_t)(n0 + row) * Kd + k0 + c * 8;
        cpa16(sbase + MMS_A_H + so, Ah + ga);
        cpa16(sbase + MMS_A_L + so, Al + ga);
        cpa16(sbase + MMS_B_H + so, Bh + gb);
        cpa16(sbase + MMS_B_L + so, Bl + gb);
    }
}

__global__ void __launch_bounds__(256, 1)
mm_mma_kernel(const __nv_bfloat16* __restrict__ Ahg, const __nv_bfloat16* __restrict__ Alg,
              const __nv_bfloat16* __restrict__ Bhg, const __nv_bfloat16* __restrict__ Blg,
              float* __restrict__ C, int Md, int Nd, int Kd) {
    extern __shared__ __align__(1024) char smem[];
    const uint32_t sb = smem_u32(smem);
    const int tid = threadIdx.x, wid = tid >> 5, lane = tid & 31;
    const int m0 = blockIdx.y * 128, n0 = blockIdx.x * 128;
    const int mw = (wid & 3) * 32;       // warp m offset
    const int nw = (wid >> 2) * 64;      // warp n offset

    float acc[2][8][4];
#pragma unroll
    for (int i = 0; i < 2; ++i)
#pragma unroll
        for (int j = 0; j < 8; ++j)
#pragma unroll
            for (int q = 0; q < 4; ++q) acc[i][j][q] = 0.f;

    const int nk = Kd >> 5;

    mm_load_stage(sb, Ahg, Alg, Bhg, Blg, m0, n0, 0, Kd, tid);
    cp_commit();

    const int jA = lane >> 3, rA = lane & 7;

    for (int it = 0; it < nk; ++it) {
        if (it + 1 < nk) {
            mm_load_stage(sb + ((it + 1) & 1) * MMS_STAGE,
                          Ahg, Alg, Bhg, Blg, m0, n0, (it + 1) << 5, Kd, tid);
            cp_commit();
            cp_wait_group<1>();
        } else {
            cp_wait_group<0>();
        }
        __syncthreads();

        const uint32_t stg = sb + (it & 1) * MMS_STAGE;

#pragma unroll
        for (int ks = 0; ks < 2; ++ks) {
            uint32_t ah[2][4], al[2][4];
#pragma unroll
            for (int i = 0; i < 2; ++i) {
                int m = mw + i * 16 + ((jA & 1) << 3) + rA;
                int c = (ks << 1) + (jA >> 1);
                uint32_t off = (uint32_t)(m * 64 + ((c ^ (m & 3)) << 4));
                ldm_x4(ah[i], stg + MMS_A_H + off);
                ldm_x4(al[i], stg + MMS_A_L + off);
            }
            uint32_t bh[8][2], bl[8][2];
#pragma unroll
            for (int p = 0; p < 4; ++p) {
                int n = nw + p * 16 + ((jA >> 1) << 3) + rA;
                int c = (ks << 1) + (jA & 1);
                uint32_t off = (uint32_t)(n * 64 + ((c ^ (n & 3)) << 4));
                uint32_t tmp[4];
                ldm_x4(tmp, stg + MMS_B_H + off);
                bh[2 * p][0] = tmp[0]; bh[2 * p][1] = tmp[1];
                bh[2 * p + 1][0] = tmp[2]; bh[2 * p + 1][1] = tmp[3];
                ldm_x4(tmp, stg + MMS_B_L + off);
                bl[2 * p][0] = tmp[0]; bl[2 * p][1] = tmp[1];
                bl[2 * p + 1][0] = tmp[2]; bl[2 * p + 1][1] = tmp[3];
            }
#pragma unroll
            for (int i = 0; i < 2; ++i)
#pragma unroll
                for (int j = 0; j < 8; ++j) {
                    mma_bf16(acc[i][j], ah[i], bh[j]);
                    mma_bf16(acc[i][j], al[i], bh[j]);
                    mma_bf16(acc[i][j], ah[i], bl[j]);
                }
        }
        __syncthreads();
    }

    // epilogue: fragment c layout: c0,c1 -> (m=l/4, n=2*(l%4)+{0,1}); c2,c3 -> m+8
#pragma unroll
    for (int i = 0; i < 2; ++i) {
        int row = m0 + mw + i * 16 + (lane >> 2);
#pragma unroll
        for (int j = 0; j < 8; ++j) {
            int col = n0 + nw + j * 8 + ((lane & 3) << 1);
            *(float2*)&C[(size_t)row * Nd + col]       = make_float2(acc[i][j][0], acc[i][j][1]);
            *(float2*)&C[(size_t)(row + 8) * Nd + col] = make_float2(acc[i][j][2], acc[i][j][3]);
        }
    }
}

// ---------------- fp32 SGEMM (tiny KR projection only) ----------------
__global__ void __launch_bounds__(256)
sgemm_kernel(const float* __restrict__ A, const float* __restrict__ B,
             float* __restrict__ C, int M, int N, int K) {
    __shared__ float As[8][128];
    __shared__ float Bs[8][128];

    const int tid = threadIdx.x;
    const int tx = tid & 15;
    const int ty = tid >> 4;
    const int m0 = blockIdx.y * 128;
    const int n0 = blockIdx.x * 128;

    const int arow = tid >> 1;
    const int acg  = (tid & 1) * 4;
    const int brow = tid >> 5;
    const int bcol = (tid & 31) * 4;

    float acc[8][8];
#pragma unroll
    for (int i = 0; i < 8; ++i)
#pragma unroll
        for (int j = 0; j < 8; ++j) acc[i][j] = 0.f;

    for (int k0 = 0; k0 < K; k0 += 8) {
        {
            float4 av = *(const float4*)&A[(size_t)(m0 + arow) * K + k0 + acg];
            As[acg + 0][arow] = av.x;
            As[acg + 1][arow] = av.y;
            As[acg + 2][arow] = av.z;
            As[acg + 3][arow] = av.w;
        }
        {
            float4 bv = make_float4(0.f, 0.f, 0.f, 0.f);
            int col = n0 + bcol;
            if (col + 3 < N) {
                bv = *(const float4*)&B[(size_t)(k0 + brow) * N + col];
            } else {
                const float* bp = &B[(size_t)(k0 + brow) * N];
                if (col + 0 < N) bv.x = bp[col + 0];
                if (col + 1 < N) bv.y = bp[col + 1];
                if (col + 2 < N) bv.z = bp[col + 2];
                if (col + 3 < N) bv.w = bp[col + 3];
            }
            Bs[brow][bcol + 0] = bv.x;
            Bs[brow][bcol + 1] = bv.y;
            Bs[brow][bcol + 2] = bv.z;
            Bs[brow][bcol + 3] = bv.w;
        }
        __syncthreads();

#pragma unroll
        for (int kk = 0; kk < 8; ++kk) {
            float a[8], bb[8];
            float4 a0 = *(const float4*)&As[kk][ty * 8];
            float4 a1 = *(const float4*)&As[kk][ty * 8 + 4];
            float4 b0 = *(const float4*)&Bs[kk][tx * 8];
            float4 b1 = *(const float4*)&Bs[kk][tx * 8 + 4];
            a[0]=a0.x; a[1]=a0.y; a[2]=a0.z; a[3]=a0.w;
            a[4]=a1.x; a[5]=a1.y; a[6]=a1.z; a[7]=a1.w;
            bb[0]=b0.x; bb[1]=b0.y; bb[2]=b0.z; bb[3]=b0.w;
            bb[4]=b1.x; bb[5]=b1.y; bb[6]=b1.z; bb[7]=b1.w;
#pragma unroll
            for (int i = 0; i < 8; ++i)
#pragma unroll
                for (int j = 0; j < 8; ++j)
                    acc[i][j] = fmaf(a[i], bb[j], acc[i][j]);
        }
        __syncthreads();
    }

#pragma unroll
    for (int i = 0; i < 8; ++i) {
        int row = m0 + ty * 8 + i;
        if (row >= M) continue;
#pragma unroll
        for (int j = 0; j < 8; ++j) {
            int col = n0 + tx * 8 + j;
            if (col < N) C[(size_t)row * N + col] = acc[i][j];
        }
    }
}

// ---------------- assemble: RoPE + concat + L2-normalize + transpose ----------------
#define LOG2_ROPE_BASE 13.287712379549449f

__global__ void __launch_bounds__(512)
assemble_kernel(const float* __restrict__ s_qk_ptr) {
    const int bl = blockIdx.x;
    const int b  = bl / Lsz;
    const int l  = bl % Lsz;
    const int w    = threadIdx.x >> 5;
    const int lane = threadIdx.x & 31;
    const float s_qk = *s_qk_ptr;

    float qv[6], kv[6];
    float ssq = 0.f, ssk = 0.f;

#pragma unroll
    for (int j = 0; j < 6; ++j) {
        int d = j * 32 + lane;
        float qx, kx;
        if (d < DHs) {
            qx = g_qc[(size_t)bl * Dsz + w * DHs + d];
            kx = g_kc[(size_t)bl * Dsz + w * DHs + d];
        } else {
            int dr = d - DHs;
            int i  = dr & 31;
            float invf = exp2f(-(float)i * (LOG2_ROPE_BASE / 32.0f));
            float ang  = (float)l * invf;
            float sn, cs;
            sincosf(ang, &sn, &cs);
            const float* qrp = &g_qr[(size_t)bl * (NHs * DHRs) + w * DHRs];
            float x1 = qrp[dr];
            float x2 = (dr < 32) ? -qrp[dr + 32] : qrp[dr - 32];
            qx = x1 * cs + x2 * sn;
            const float* krp = &g_kr[(size_t)bl * DHRs];
            float y1 = krp[dr];
            float y2 = (dr < 32) ? -krp[dr + 32] : krp[dr - 32];
            kx = y1 * cs + y2 * sn;
        }
        qv[j] = qx; kv[j] = kx;
        ssq += qx * qx; ssk += kx * kx;
    }
#pragma unroll
    for (int o = 16; o; o >>= 1) {
        ssq += __shfl_xor_sync(0xffffffffu, ssq, o);
        ssk += __shfl_xor_sync(0xffffffffu, ssk, o);
    }
    float qn = s_qk / fmaxf(sqrtf(ssq), 1e-12f);
    float kn = 1.0f / fmaxf(sqrtf(ssk), 1e-12f);

    size_t base = ((size_t)(b * NHs + w) * Lsz + l);
#pragma unroll
    for (int j = 0; j < 6; ++j) {
        int d = j * 32 + lane;
        g_Q[base * DTOT + d] = qv[j] * qn;
        g_K[base * DTOT + d] = kv[j] * kn;
    }
#pragma unroll
    for (int dd = 0; dd < 4; ++dd) {
        int d = dd * 32 + lane;
        g_V[base * DHs + d] = g_vt[(size_t)bl * Dsz + w * DHs + d];
    }
}

// ---------------- causal flash attention, fp32, 64x64 tiles ----------------
#define FBQ 64
#define FBK 64
#define SQ  193
#define FLASH_SMEM_BYTES ((FBQ*SQ + FBK*SQ + FBK*DHs + FBQ*FBK) * sizeof(float))

__global__ void __launch_bounds__(256)
flash_kernel() {
    extern __shared__ float sm[];
    float* Qs = sm;
    float* Ks = Qs + FBQ * SQ;
    float* Vs = Ks + FBK * SQ;
    float* Ps = Vs + FBK * DHs;

    const int qt = blockIdx.x;
    const int h  = blockIdx.y;
    const int b  = blockIdx.z;
    const int tid  = threadIdx.x;
    const int w    = tid >> 5;
    const int lane = tid & 31;
    const int q0 = qt * FBQ;

    const float* Qg  = g_Q + ((size_t)(b * NHs + h) * Lsz + q0) * DTOT;
    const float* Kg0 = g_K + (size_t)(b * NHs + h) * Lsz * DTOT;
    const float* Vg0 = g_V + (size_t)(b * NHs + h) * Lsz * DHs;

    for (int idx = tid; idx < FBQ * DTOT; idx += 256)
        Qs[(idx / DTOT) * SQ + (idx % DTOT)] = Qg[idx];

    float m[8], lsum[8], acc[8][4];
#pragma unroll
    for (int r = 0; r < 8; ++r) {
        m[r] = -1e30f; lsum[r] = 0.f;
#pragma unroll
        for (int dd = 0; dd < 4; ++dd) acc[r][dd] = 0.f;
    }

    for (int kt = 0; kt <= qt; ++kt) {
        __syncthreads();
        const int k0 = kt * FBK;
        for (int idx = tid; idx < FBK * DTOT; idx += 256)
            Ks[(idx / DTOT) * SQ + (idx % DTOT)] = Kg0[(size_t)k0 * DTOT + idx];
        for (int idx = tid; idx < FBK * DHs; idx += 256)
            Vs[idx] = Vg0[(size_t)k0 * DHs + idx];
        __syncthreads();

        const bool diag = (kt == qt);
        const int c0 = lane, c1 = lane + 32;

#pragma unroll
        for (int r = 0; r < 8; ++r) {
            const int row = w * 8 + r;
            const float* qp  = Qs + row * SQ;
            const float* kp0 = Ks + c0 * SQ;
            const float* kp1 = Ks + c1 * SQ;
            float s0 = 0.f, s1 = 0.f;
#pragma unroll 8
            for (int k = 0; k < DTOT; ++k) {
                float qvv = qp[k];
                s0 = fmaf(qvv, kp0[k], s0);
                s1 = fmaf(qvv, kp1[k], s1);
            }
            if (diag) {
                int rg = q0 + row;
                if (k0 + c0 > rg) s0 = -1e30f;
                if (k0 + c1 > rg) s1 = -1e30f;
            }
            float mt = fmaxf(s0, s1);
#pragma unroll
            for (int o = 16; o; o >>= 1)
                mt = fmaxf(mt, __shfl_xor_sync(0xffffffffu, mt, o));
            float mnew = fmaxf(m[r], mt);
            float p0 = expf(s0 - mnew);
            float p1 = expf(s1 - mnew);
            float rs = p0 + p1;
#pragma unroll
            for (int o = 16; o; o >>= 1)
                rs += __shfl_xor_sync(0xffffffffu, rs, o);
            float scale = expf(m[r] - mnew);
            m[r] = mnew;
            lsum[r] = lsum[r] * scale + rs;
#pragma unroll
            for (int dd = 0; dd < 4; ++dd) acc[r][dd] *= scale;
            Ps[row * FBK + c0] = p0;
            Ps[row * FBK + c1] = p1;
        }
        __syncwarp();

#pragma unroll 4
        for (int c = 0; c < FBK; ++c) {
            float v0 = Vs[c * DHs +  0 + lane];
            float v1 = Vs[c * DHs + 32 + lane];
            float v2 = Vs[c * DHs + 64 + lane];
            float v3 = Vs[c * DHs + 96 + lane];
            const float* pr = Ps + (w * 8) * FBK + c;
#pragma unroll
            for (int r = 0; r < 8; ++r) {
                float p = pr[r * FBK];
                acc[r][0] = fmaf(p, v0, acc[r][0]);
                acc[r][1] = fmaf(p, v1, acc[r][1]);
                acc[r][2] = fmaf(p, v2, acc[r][2]);
                acc[r][3] = fmaf(p, v3, acc[r][3]);
            }
        }
    }

#pragma unroll
    for (int r = 0; r < 8; ++r) {
        float inv = 1.0f / lsum[r];
        int row = q0 + w * 8 + r;
        size_t ob = ((size_t)(b * Lsz + row)) * Dsz + h * DHs;
#pragma unroll
        for (int dd = 0; dd < 4; ++dd)
            g_ao[ob + dd * 32 + lane] = acc[r][dd] * inv;
    }
}

// ---------------- launcher ----------------
extern "C" void kernel_launch(void* const* d_in, const int* in_sizes, int n_in,
                              void* d_out, int out_size) {
    const float* x     = (const float*)d_in[0];
    const float* W_DKV = (const float*)d_in[1];
    const float* W_UK  = (const float*)d_in[2];
    const float* W_UV  = (const float*)d_in[3];
    const float* W_DQ  = (const float*)d_in[4];
    const float* W_UQ  = (const float*)d_in[5];
    const float* W_QR  = (const float*)d_in[6];
    const float* W_KR  = (const float*)d_in[7];
    const float* W_O   = (const float*)d_in[8];
    const float* s_qk  = (const float*)d_in[9];
    float* out = (float*)d_out;

    float *ckv, *cq, *kc, *vt, *qc, *qr, *kr, *ao;
    cudaGetSymbolAddress((void**)&ckv, g_ckv);
    cudaGetSymbolAddress((void**)&cq,  g_cq);
    cudaGetSymbolAddress((void**)&kc,  g_kc);
    cudaGetSymbolAddress((void**)&vt,  g_vt);
    cudaGetSymbolAddress((void**)&qc,  g_qc);
    cudaGetSymbolAddress((void**)&qr,  g_qr);
    cudaGetSymbolAddress((void**)&kr,  g_kr);
    cudaGetSymbolAddress((void**)&ao,  g_ao);

    __nv_bfloat16 *xh, *xl, *ckvh, *ckvl, *cqh, *cql, *aoh, *aol;
    __nv_bfloat16 *wdkvh, *wdkvl, *wdqh, *wdql, *wukh, *wukl, *wuvh, *wuvl;
    __nv_bfloat16 *wuqh, *wuql, *wqrh, *wqrl, *woh, *wol;
    cudaGetSymbolAddress((void**)&xh, g_xh);     cudaGetSymbolAddress((void**)&xl, g_xl);
    cudaGetSymbolAddress((void**)&ckvh, g_ckvh); cudaGetSymbolAddress((void**)&ckvl, g_ckvl);
    cudaGetSymbolAddress((void**)&cqh, g_cqh);   cudaGetSymbolAddress((void**)&cql, g_cql);
    cudaGetSymbolAddress((void**)&aoh, g_aoh);   cudaGetSymbolAddress((void**)&aol, g_aol);
    cudaGetSymbolAddress((void**)&wdkvh, g_wdkvh); cudaGetSymbolAddress((void**)&wdkvl, g_wdkvl);
    cudaGetSymbolAddress((void**)&wdqh, g_wdqh);   cudaGetSymbolAddress((void**)&wdql, g_wdql);
    cudaGetSymbolAddress((void**)&wukh, g_wukh);   cudaGetSymbolAddress((void**)&wukl, g_wukl);
    cudaGetSymbolAddress((void**)&wuvh, g_wuvh);   cudaGetSymbolAddress((void**)&wuvl, g_wuvl);
    cudaGetSymbolAddress((void**)&wuqh, g_wuqh);   cudaGetSymbolAddress((void**)&wuql, g_wuql);
    cudaGetSymbolAddress((void**)&wqrh, g_wqrh);   cudaGetSymbolAddress((void**)&wqrl, g_wqrl);
    cudaGetSymbolAddress((void**)&woh, g_woh);     cudaGetSymbolAddress((void**)&wol, g_wol);

    cudaFuncSetAttribute(mm_mma_kernel, cudaFuncAttributeMaxDynamicSharedMemorySize, MM_SMEM);
    cudaFuncSetAttribute(flash_kernel, cudaFuncAttributeMaxDynamicSharedMemorySize,
                         (int)FLASH_SMEM_BYTES);

    dim3 tsb(32, 8);
    // weight transposes+splits: tsplit(W, Th, Tl, K, N), grid (N/32, K/32)
    tsplit_kernel<<<dim3(DCs/32, Dsz/32), tsb>>>(W_DKV, wdkvh, wdkvl, Dsz, DCs);
    tsplit_kernel<<<dim3(DCs/32, Dsz/32), tsb>>>(W_DQ,  wdqh,  wdql,  Dsz, DCs);
    tsplit_kernel<<<dim3(Dsz/32, DCs/32), tsb>>>(W_UK,  wukh,  wukl,  DCs, Dsz);
    tsplit_kernel<<<dim3(Dsz/32, DCs/32), tsb>>>(W_UV,  wuvh,  wuvl,  DCs, Dsz);
    tsplit_kernel<<<dim3(Dsz/32, DCs/32), tsb>>>(W_UQ,  wuqh,  wuql,  DCs, Dsz);
    tsplit_kernel<<<dim3((NHs*DHRs)/32, DCs/32), tsb>>>(W_QR, wqrh, wqrl, DCs, NHs*DHRs);
    tsplit_kernel<<<dim3(Dsz/32, Dsz/32), tsb>>>(W_O,   woh,   wol,   Dsz, Dsz);

    // split x
    {
        int n = Msz * Dsz;
        split_kernel<<<(n + 255) / 256, 256>>>(x, xh, xl, n);
    }

    // down-projections (tensor core) + k_rope (fp32)
    mm_mma_kernel<<<dim3(DCs/128, Msz/128), 256, MM_SMEM>>>(xh, xl, wdkvh, wdkvl, ckv, Msz, DCs, Dsz);
    mm_mma_kernel<<<dim3(DCs/128, Msz/128), 256, MM_SMEM>>>(xh, xl, wdqh,  wdql,  cq,  Msz, DCs, Dsz);
    sgemm_kernel<<<dim3(1, Msz/128), 256>>>(x, W_KR, kr, Msz, DHRs, Dsz);

    // split intermediates
    {
        int n = Msz * DCs;
        split_kernel<<<(n + 255) / 256, 256>>>(ckv, ckvh, ckvl, n);
        split_kernel<<<(n + 255) / 256, 256>>>(cq,  cqh,  cql,  n);
    }

    // up-projections (tensor core)
    mm_mma_kernel<<<dim3(Dsz/128, Msz/128), 256, MM_SMEM>>>(ckvh, ckvl, wukh, wukl, kc, Msz, Dsz, DCs);
    mm_mma_kernel<<<dim3(Dsz/128, Msz/128), 256, MM_SMEM>>>(ckvh, ckvl, wuvh, wuvl, vt, Msz, Dsz, DCs);
    mm_mma_kernel<<<dim3(Dsz/128, Msz/128), 256, MM_SMEM>>>(cqh,  cql,  wuqh, wuql, qc, Msz, Dsz, DCs);
    mm_mma_kernel<<<dim3((NHs*DHRs)/128, Msz/128), 256, MM_SMEM>>>(cqh, cql, wqrh, wqrl, qr, Msz, NHs*DHRs, DCs);

    // RoPE + concat + normalize + transpose
    assemble_kernel<<<Msz, 512>>>(s_qk);

    // causal flash attention
    flash_kernel<<<dim3(Lsz / FBQ, NHs, Bsz), 256, FLASH_SMEM_BYTES>>>();

    // output projection (tensor core)
    {
        int n = Msz * Dsz;
        split_kernel<<<(n + 255) / 256, 256>>>(ao, aoh, aol, n);
    }
    mm_mma_kernel<<<dim3(Dsz/128, Msz/128), 256, MM_SMEM>>>(aoh, aol, woh, wol, out, Msz, Dsz, Dsz);
}

// round 5
// speedup vs baseline: 4.0625x; 2.8428x over previous
#include <cuda_runtime.h>
#include <cuda_bf16.h>
#include <math.h>
#include <stdint.h>

// ---------------- problem constants ----------------
#define Bsz   4
#define Lsz   2048
#define Dsz   2048
#define NHs   16
#define DHs   128
#define DHRs  64
#define DCs   1024
#define DTOT  (DHs + DHRs)     // 192
#define Msz   (Bsz * Lsz)      // 8192

// ---------------- fp32 scratch ----------------
__device__ float g_kc [Msz * Dsz];
__device__ float g_vt [Msz * Dsz];
__device__ float g_qc [Msz * Dsz];
__device__ float g_qr [Msz * (NHs * DHRs)];
__device__ float g_kr2[Msz * 128];            // padded KR output (cols 64..127 unused)

// ---------------- bf16 split scratch ----------------
__device__ __align__(256) __nv_bfloat16 g_xh [Msz * Dsz];
__device__ __align__(256) __nv_bfloat16 g_xl [Msz * Dsz];
__device__ __align__(256) __nv_bfloat16 g_ckvh[Msz * DCs];
__device__ __align__(256) __nv_bfloat16 g_ckvl[Msz * DCs];
__device__ __align__(256) __nv_bfloat16 g_cqh [Msz * DCs];
__device__ __align__(256) __nv_bfloat16 g_cql [Msz * DCs];
__device__ __align__(256) __nv_bfloat16 g_aoh [Msz * Dsz];
__device__ __align__(256) __nv_bfloat16 g_aol [Msz * Dsz];
// attention operands, hi/lo
__device__ __align__(256) __nv_bfloat16 g_Qh [Bsz*NHs*Lsz*DTOT], g_Ql [Bsz*NHs*Lsz*DTOT];
__device__ __align__(256) __nv_bfloat16 g_Kh [Bsz*NHs*Lsz*DTOT], g_Kl [Bsz*NHs*Lsz*DTOT];
__device__ __align__(256) __nv_bfloat16 g_Vh [Bsz*NHs*Lsz*DHs],  g_Vl [Bsz*NHs*Lsz*DHs];
// transposed weights [N x K], hi/lo
__device__ __align__(256) __nv_bfloat16 g_wdkvh[DCs * Dsz], g_wdkvl[DCs * Dsz];
__device__ __align__(256) __nv_bfloat16 g_wdqh [DCs * Dsz], g_wdql [DCs * Dsz];
__device__ __align__(256) __nv_bfloat16 g_wukh [Dsz * DCs], g_wukl [Dsz * DCs];
__device__ __align__(256) __nv_bfloat16 g_wuvh [Dsz * DCs], g_wuvl [Dsz * DCs];
__device__ __align__(256) __nv_bfloat16 g_wuqh [Dsz * DCs], g_wuql [Dsz * DCs];
__device__ __align__(256) __nv_bfloat16 g_wqrh [(NHs*DHRs) * DCs], g_wqrl[(NHs*DHRs) * DCs];
__device__ __align__(256) __nv_bfloat16 g_wkrh [128 * Dsz], g_wkrl [128 * Dsz];  // zero-padded rows 64..127
__device__ __align__(256) __nv_bfloat16 g_woh  [Dsz * Dsz], g_wol  [Dsz * Dsz];

// ---------------- PTX helpers (baseline ISA only) ----------------
__device__ __forceinline__ uint32_t smem_u32(const void* p) {
    uint32_t a;
    asm("{ .reg .u64 t; cvta.to.shared.u64 t, %1; cvt.u32.u64 %0, t; }" : "=r"(a) : "l"(p));
    return a;
}
__device__ __forceinline__ void cpa16(uint32_t s, const void* g) {
    asm volatile("cp.async.cg.shared.global [%0], [%1], 16;" :: "r"(s), "l"(g) : "memory");
}
__device__ __forceinline__ void cp_commit() {
    asm volatile("cp.async.commit_group;" ::: "memory");
}
template <int N> __device__ __forceinline__ void cp_wait_group() {
    asm volatile("cp.async.wait_group %0;" :: "n"(N) : "memory");
}
__device__ __forceinline__ void ldm_x4(uint32_t* r, uint32_t addr) {
    asm volatile("ldmatrix.sync.aligned.m8n8.x4.shared.b16 {%0,%1,%2,%3}, [%4];"
                 : "=r"(r[0]), "=r"(r[1]), "=r"(r[2]), "=r"(r[3]) : "r"(addr));
}
__device__ __forceinline__ void ldm_x4_t(uint32_t* r, uint32_t addr) {
    asm volatile("ldmatrix.sync.aligned.m8n8.x4.trans.shared.b16 {%0,%1,%2,%3}, [%4];"
                 : "=r"(r[0]), "=r"(r[1]), "=r"(r[2]), "=r"(r[3]) : "r"(addr));
}
__device__ __forceinline__ void mma_bf16(float* c, const uint32_t* a, const uint32_t* b) {
    asm volatile(
        "mma.sync.aligned.m16n8k16.row.col.f32.bf16.bf16.f32 "
        "{%0,%1,%2,%3}, {%4,%5,%6,%7}, {%8,%9}, {%0,%1,%2,%3};"
        : "+f"(c[0]), "+f"(c[1]), "+f"(c[2]), "+f"(c[3])
        : "r"(a[0]), "r"(a[1]), "r"(a[2]), "r"(a[3]), "r"(b[0]), "r"(b[1]));
}

// ---------------- split / transpose-split conversions ----------------
__global__ void split_kernel(const float* __restrict__ src,
                             __nv_bfloat16* __restrict__ hi,
                             __nv_bfloat16* __restrict__ lo, int n) {
    int i = blockIdx.x * 256 + threadIdx.x;
    if (i < n) {
        float x = src[i];
        __nv_bfloat16 h = __float2bfloat16(x);
        float r = x - __bfloat162float(h);
        hi[i] = h;
        lo[i] = __float2bfloat16(r);
    }
}

// W[K x N] row-major -> Th/Tl [N x K] row-major bf16 hi/lo  (Kt = row stride of T)
__global__ void tsplit_kernel(const float* __restrict__ W,
                              __nv_bfloat16* __restrict__ Th,
                              __nv_bfloat16* __restrict__ Tl, int K, int N) {
    __shared__ float t[32][33];
    int kb = blockIdx.y * 32, nb = blockIdx.x * 32;
    int tx = threadIdx.x, ty = threadIdx.y;    // (32, 8)
#pragma unroll
    for (int r = 0; r < 32; r += 8)
        t[ty + r][tx] = W[(size_t)(kb + ty + r) * N + nb + tx];
    __syncthreads();
#pragma unroll
    for (int r = 0; r < 32; r += 8) {
        float x = t[tx][ty + r];
        __nv_bfloat16 h = __float2bfloat16(x);
        float res = x - __bfloat162float(h);
        size_t o = (size_t)(nb + ty + r) * K + kb + tx;
        Th[o] = h;
        Tl[o] = __float2bfloat16(res);
    }
}

// ---------------- mma.sync bf16 split-3 GEMM ----------------
// C[M,N] = A[M,K] @ Bt[N,K]^T.  Output: fp32 (Cf) OR bf16 hi/lo pair (Ch/Cl).
#define MMS_A_H 0
#define MMS_A_L 8192
#define MMS_B_H 16384
#define MMS_B_L 24576
#define MMS_STAGE 32768
#define MM_SMEM (2 * MMS_STAGE)

__device__ __forceinline__ void mm_load_stage(
    uint32_t sbase,
    const __nv_bfloat16* __restrict__ Ah, const __nv_bfloat16* __restrict__ Al,
    const __nv_bfloat16* __restrict__ Bh, const __nv_bfloat16* __restrict__ Bl,
    int m0, int n0, int k0, int Kd, int tid)
{
#pragma unroll
    for (int t = 0; t < 2; ++t) {
        int idx = tid + t * 256;
        int row = idx >> 2;
        int c   = idx & 3;
        uint32_t so = (uint32_t)(row * 64 + ((c ^ (row & 3)) << 4));
        size_t ga = (size_t)(m0 + row) * Kd + k0 + c * 8;
        size_t gb = (size_t)(n0 + row) * Kd + k0 + c * 8;
        cpa16(sbase + MMS_A_H + so, Ah + ga);
        cpa16(sbase + MMS_A_L + so, Al + ga);
        cpa16(sbase + MMS_B_H + so, Bh + gb);
        cpa16(sbase + MMS_B_L + so, Bl + gb);
    }
}

__global__ void __launch_bounds__(256, 1)
mm_mma_kernel(const __nv_bfloat16* __restrict__ Ahg, const __nv_bfloat16* __restrict__ Alg,
              const __nv_bfloat16* __restrict__ Bhg, const __nv_bfloat16* __restrict__ Blg,
              float* __restrict__ Cf,
              __nv_bfloat16* __restrict__ Ch, __nv_bfloat16* __restrict__ Cl,
              int Md, int Nd, int Kd) {
    extern __shared__ __align__(1024) char smem[];
    const uint32_t sb = smem_u32(smem);
    const int tid = threadIdx.x, wid = tid >> 5, lane = tid & 31;
    const int m0 = blockIdx.y * 128, n0 = blockIdx.x * 128;
    const int mw = (wid & 3) * 32;
    const int nw = (wid >> 2) * 64;

    float acc[2][8][4];
#pragma unroll
    for (int i = 0; i < 2; ++i)
#pragma unroll
        for (int j = 0; j < 8; ++j)
#pragma unroll
            for (int q = 0; q < 4; ++q) acc[i][j][q] = 0.f;

    const int nk = Kd >> 5;
    mm_load_stage(sb, Ahg, Alg, Bhg, Blg, m0, n0, 0, Kd, tid);
    cp_commit();

    const int jA = lane >> 3, rA = lane & 7;

    for (int it = 0; it < nk; ++it) {
        if (it + 1 < nk) {
            mm_load_stage(sb + ((it + 1) & 1) * MMS_STAGE,
                          Ahg, Alg, Bhg, Blg, m0, n0, (it + 1) << 5, Kd, tid);
            cp_commit();
            cp_wait_group<1>();
        } else {
            cp_wait_group<0>();
        }
        __syncthreads();

        const uint32_t stg = sb + (it & 1) * MMS_STAGE;

#pragma unroll
        for (int ks = 0; ks < 2; ++ks) {
            uint32_t ah[2][4], al[2][4];
#pragma unroll
            for (int i = 0; i < 2; ++i) {
                int m = mw + i * 16 + ((jA & 1) << 3) + rA;
                int c = (ks << 1) + (jA >> 1);
                uint32_t off = (uint32_t)(m * 64 + ((c ^ (m & 3)) << 4));
                ldm_x4(ah[i], stg + MMS_A_H + off);
                ldm_x4(al[i], stg + MMS_A_L + off);
            }
            uint32_t bh[8][2], bl[8][2];
#pragma unroll
            for (int p = 0; p < 4; ++p) {
                int n = nw + p * 16 + ((jA >> 1) << 3) + rA;
                int c = (ks << 1) + (jA & 1);
                uint32_t off = (uint32_t)(n * 64 + ((c ^ (n & 3)) << 4));
                uint32_t tmp[4];
                ldm_x4(tmp, stg + MMS_B_H + off);
                bh[2 * p][0] = tmp[0]; bh[2 * p][1] = tmp[1];
                bh[2 * p + 1][0] = tmp[2]; bh[2 * p + 1][1] = tmp[3];
                ldm_x4(tmp, stg + MMS_B_L + off);
                bl[2 * p][0] = tmp[0]; bl[2 * p][1] = tmp[1];
                bl[2 * p + 1][0] = tmp[2]; bl[2 * p + 1][1] = tmp[3];
            }
#pragma unroll
            for (int i = 0; i < 2; ++i)
#pragma unroll
                for (int j = 0; j < 8; ++j) {
                    mma_bf16(acc[i][j], ah[i], bh[j]);
                    mma_bf16(acc[i][j], al[i], bh[j]);
                    mma_bf16(acc[i][j], ah[i], bl[j]);
                }
        }
        __syncthreads();
    }

#pragma unroll
    for (int i = 0; i < 2; ++i) {
        int row = m0 + mw + i * 16 + (lane >> 2);
#pragma unroll
        for (int j = 0; j < 8; ++j) {
            int col = n0 + nw + j * 8 + ((lane & 3) << 1);
            if (Cf) {
                *(float2*)&Cf[(size_t)row * Nd + col]       = make_float2(acc[i][j][0], acc[i][j][1]);
                *(float2*)&Cf[(size_t)(row + 8) * Nd + col] = make_float2(acc[i][j][2], acc[i][j][3]);
            } else {
#pragma unroll
                for (int hh = 0; hh < 2; ++hh) {
                    float v0 = acc[i][j][2 * hh], v1 = acc[i][j][2 * hh + 1];
                    __nv_bfloat162 h2, l2;
                    h2.x = __float2bfloat16(v0); h2.y = __float2bfloat16(v1);
                    l2.x = __float2bfloat16(v0 - __bfloat162float(h2.x));
                    l2.y = __float2bfloat16(v1 - __bfloat162float(h2.y));
                    size_t o = (size_t)(row + 8 * hh) * Nd + col;
                    *(__nv_bfloat162*)&Ch[o] = h2;
                    *(__nv_bfloat162*)&Cl[o] = l2;
                }
            }
        }
    }
}

// ---------------- assemble: RoPE + concat + normalize -> bf16 hi/lo Q,K,V ----------------
#define LOG2_ROPE_BASE 13.287712379549449f

__global__ void __launch_bounds__(512)
assemble_kernel(const float* __restrict__ s_qk_ptr) {
    const int bl = blockIdx.x;
    const int b  = bl / Lsz;
    const int l  = bl % Lsz;
    const int w    = threadIdx.x >> 5;
    const int lane = threadIdx.x & 31;
    const float s_qk = *s_qk_ptr;

    float qv[6], kv[6];
    float ssq = 0.f, ssk = 0.f;

#pragma unroll
    for (int j = 0; j < 6; ++j) {
        int d = j * 32 + lane;
        float qx, kx;
        if (d < DHs) {
            qx = g_qc[(size_t)bl * Dsz + w * DHs + d];
            kx = g_kc[(size_t)bl * Dsz + w * DHs + d];
        } else {
            int dr = d - DHs;
            int i  = dr & 31;
            float invf = exp2f(-(float)i * (LOG2_ROPE_BASE / 32.0f));
            float ang  = (float)l * invf;
            float sn, cs;
            sincosf(ang, &sn, &cs);
            const float* qrp = &g_qr[(size_t)bl * (NHs * DHRs) + w * DHRs];
            float x1 = qrp[dr];
            float x2 = (dr < 32) ? -qrp[dr + 32] : qrp[dr - 32];
            qx = x1 * cs + x2 * sn;
            const float* krp = &g_kr2[(size_t)bl * 128];
            float y1 = krp[dr];
            float y2 = (dr < 32) ? -krp[dr + 32] : krp[dr - 32];
            kx = y1 * cs + y2 * sn;
        }
        qv[j] = qx; kv[j] = kx;
        ssq += qx * qx; ssk += kx * kx;
    }
#pragma unroll
    for (int o = 16; o; o >>= 1) {
        ssq += __shfl_xor_sync(0xffffffffu, ssq, o);
        ssk += __shfl_xor_sync(0xffffffffu, ssk, o);
    }
    float qn = s_qk / fmaxf(sqrtf(ssq), 1e-12f);
    float kn = 1.0f / fmaxf(sqrtf(ssk), 1e-12f);

    size_t base = ((size_t)(b * NHs + w) * Lsz + l);
#pragma unroll
    for (int j = 0; j < 6; ++j) {
        int d = j * 32 + lane;
        float q = qv[j] * qn, k = kv[j] * kn;
        __nv_bfloat16 qh = __float2bfloat16(q);
        __nv_bfloat16 kh = __float2bfloat16(k);
        g_Qh[base * DTOT + d] = qh;
        g_Ql[base * DTOT + d] = __float2bfloat16(q - __bfloat162float(qh));
        g_Kh[base * DTOT + d] = kh;
        g_Kl[base * DTOT + d] = __float2bfloat16(k - __bfloat162float(kh));
    }
#pragma unroll
    for (int dd = 0; dd < 4; ++dd) {
        int d = dd * 32 + lane;
        float v = g_vt[(size_t)bl * Dsz + w * DHs + d];
        __nv_bfloat16 vh = __float2bfloat16(v);
        g_Vh[base * DHs + d] = vh;
        g_Vl[base * DHs + d] = __float2bfloat16(v - __bfloat162float(vh));
    }
}

// ---------------- tensor-core causal flash attention (split-3 bf16) ----------------
#define FQ 128
#define FK 64
// smem byte offsets
#define SQH 0
#define SQL (SQH + FQ*384)
#define SKH (SQL + FQ*384)
#define SKL (SKH + FK*384)
#define SVH (SKL + FK*384)
#define SVL (SVH + FK*256)
#define SPH (SVL + FK*256)
#define SPL (SPH + FQ*128)
#define FLASH_SMEM (SPL + FQ*128)   // 212992 bytes

__device__ __forceinline__ void fl_load_qk(
    uint32_t sb, uint32_t offH, uint32_t offL, int rows,
    const __nv_bfloat16* __restrict__ Gh, const __nv_bfloat16* __restrict__ Gl,
    size_t gbase, int tid)
{
    for (int idx = tid; idx < rows * 24; idx += 256) {
        int r = idx / 24, c = idx % 24;
        uint32_t so = (uint32_t)(r * 384 + ((c ^ (r & 7)) << 4));
        size_t g = gbase + (size_t)r * DTOT + c * 8;
        cpa16(sb + offH + so, Gh + g);
        cpa16(sb + offL + so, Gl + g);
    }
}
__device__ __forceinline__ void fl_load_v(
    uint32_t sb, const __nv_bfloat16* __restrict__ Gh, const __nv_bfloat16* __restrict__ Gl,
    size_t gbase, int tid)
{
    for (int idx = tid; idx < FK * 16; idx += 256) {
        int r = idx >> 4, c = idx & 15;
        uint32_t so = (uint32_t)(r * 256 + ((c ^ (r & 7)) << 4));
        size_t g = gbase + (size_t)r * DHs + c * 8;
        cpa16(sb + SVH + so, Gh + g);
        cpa16(sb + SVL + so, Gl + g);
    }
}

__global__ void __launch_bounds__(256, 1)
flashmma_kernel() {
    extern __shared__ __align__(1024) char sm[];
    const uint32_t sb = smem_u32(sm);
    const int tid = threadIdx.x, w = tid >> 5, lane = tid & 31;
    const int qt = (int)(gridDim.x - 1u - blockIdx.x);
    const int h = blockIdx.y, b = blockIdx.z;
    const int q0 = qt * FQ;
    const int mw = w * 16;
    const int jA = lane >> 3, rA = lane & 7;

    const size_t qkb = (size_t)(b * NHs + h) * Lsz;
    fl_load_qk(sb, SQH, SQL, FQ, g_Qh, g_Ql, (qkb + q0) * DTOT, tid);
    cp_commit();
    fl_load_qk(sb, SKH, SKL, FK, g_Kh, g_Kl, qkb * DTOT, tid);
    cp_commit();
    fl_load_v(sb, g_Vh, g_Vl, qkb * DHs, tid);
    cp_commit();

    float oacc[16][4];
#pragma unroll
    for (int j = 0; j < 16; ++j)
#pragma unroll
        for (int q = 0; q < 4; ++q) oacc[j][q] = 0.f;
    float m0 = -1e30f, m1 = -1e30f, l0 = 0.f, l1 = 0.f;

    const int nkt = 2 * qt + 2;
    const int r0loc = mw + (lane >> 2);
    const int gr0 = q0 + r0loc;

    for (int kt = 0; kt < nkt; ++kt) {
        cp_wait_group<1>();
        __syncthreads();

        // ---- S = Q K^T (split-3) ----
        float sacc[8][4];
#pragma unroll
        for (int j = 0; j < 8; ++j)
#pragma unroll
            for (int q = 0; q < 4; ++q) sacc[j][q] = 0.f;

#pragma unroll
        for (int ks = 0; ks < 12; ++ks) {
            int arow = mw + ((jA & 1) << 3) + rA;
            int achk = ks * 2 + (jA >> 1);
            uint32_t aoff = (uint32_t)(arow * 384 + ((achk ^ (arow & 7)) << 4));
            uint32_t ah[4], al[4];
            ldm_x4(ah, sb + SQH + aoff);
            ldm_x4(al, sb + SQL + aoff);
            uint32_t bh[8][2], bl[8][2];
#pragma unroll
            for (int p = 0; p < 4; ++p) {
                int brow = p * 16 + ((jA >> 1) << 3) + rA;
                int bchk = ks * 2 + (jA & 1);
                uint32_t boff = (uint32_t)(brow * 384 + ((bchk ^ (brow & 7)) << 4));
                uint32_t tmp[4];
                ldm_x4(tmp, sb + SKH + boff);
                bh[2 * p][0] = tmp[0]; bh[2 * p][1] = tmp[1];
                bh[2 * p + 1][0] = tmp[2]; bh[2 * p + 1][1] = tmp[3];
                ldm_x4(tmp, sb + SKL + boff);
                bl[2 * p][0] = tmp[0]; bl[2 * p][1] = tmp[1];
                bl[2 * p + 1][0] = tmp[2]; bl[2 * p + 1][1] = tmp[3];
            }
#pragma unroll
            for (int j = 0; j < 8; ++j) {
                mma_bf16(sacc[j], ah, bh[j]);
                mma_bf16(sacc[j], al, bh[j]);
                mma_bf16(sacc[j], ah, bl[j]);
            }
        }

        // ---- causal mask (last two k-tiles only) ----
        if (kt >= 2 * qt) {
            int k0 = kt * FK;
#pragma unroll
            for (int j = 0; j < 8; ++j) {
                int col = k0 + j * 8 + ((lane & 3) << 1);
                if (col > gr0)     sacc[j][0] = -1e30f;
                if (col + 1 > gr0) sacc[j][1] = -1e30f;
                if (col > gr0 + 8)     sacc[j][2] = -1e30f;
                if (col + 1 > gr0 + 8) sacc[j][3] = -1e30f;
            }
        }

        // ---- online softmax ----
        float mx0 = -1e30f, mx1 = -1e30f;
#pragma unroll
        for (int j = 0; j < 8; ++j) {
            mx0 = fmaxf(mx0, fmaxf(sacc[j][0], sacc[j][1]));
            mx1 = fmaxf(mx1, fmaxf(sacc[j][2], sacc[j][3]));
        }
#pragma unroll
        for (int o = 1; o <= 2; o <<= 1) {
            mx0 = fmaxf(mx0, __shfl_xor_sync(0xffffffffu, mx0, o));
            mx1 = fmaxf(mx1, __shfl_xor_sync(0xffffffffu, mx1, o));
        }
        float mn0 = fmaxf(m0, mx0), mn1 = fmaxf(m1, mx1);
        float sc0 = __expf(m0 - mn0), sc1 = __expf(m1 - mn1);
        m0 = mn0; m1 = mn1;

        float rs0 = 0.f, rs1 = 0.f;
        const int pr0 = r0loc, pr1 = r0loc + 8;
        const uint32_t pbyte = (uint32_t)((lane & 3) << 2);
#pragma unroll
        for (int j = 0; j < 8; ++j) {
            float p0 = __expf(sacc[j][0] - mn0);
            float p1 = __expf(sacc[j][1] - mn0);
            float p2 = __expf(sacc[j][2] - mn1);
            float p3 = __expf(sacc[j][3] - mn1);
            rs0 += p0 + p1; rs1 += p2 + p3;
            __nv_bfloat162 h2, l2;
            h2.x = __float2bfloat16(p0); h2.y = __float2bfloat16(p1);
            l2.x = __float2bfloat16(p0 - __bfloat162float(h2.x));
            l2.y = __float2bfloat16(p1 - __bfloat162float(h2.y));
            uint32_t off0 = (uint32_t)(pr0 * 128 + ((j ^ (pr0 & 7)) << 4)) + pbyte;
            *(__nv_bfloat162*)(sm + SPH + off0) = h2;
            *(__nv_bfloat162*)(sm + SPL + off0) = l2;
            h2.x = __float2bfloat16(p2); h2.y = __float2bfloat16(p3);
            l2.x = __float2bfloat16(p2 - __bfloat162float(h2.x));
            l2.y = __float2bfloat16(p3 - __bfloat162float(h2.y));
            uint32_t off1 = (uint32_t)(pr1 * 128 + ((j ^ (pr1 & 7)) << 4)) + pbyte;
            *(__nv_bfloat162*)(sm + SPH + off1) = h2;
            *(__nv_bfloat162*)(sm + SPL + off1) = l2;
        }
#pragma unroll
        for (int o = 1; o <= 2; o <<= 1) {
            rs0 += __shfl_xor_sync(0xffffffffu, rs0, o);
            rs1 += __shfl_xor_sync(0xffffffffu, rs1, o);
        }
        l0 = l0 * sc0 + rs0;
        l1 = l1 * sc1 + rs1;
#pragma unroll
        for (int j = 0; j < 16; ++j) {
            oacc[j][0] *= sc0; oacc[j][1] *= sc0;
            oacc[j][2] *= sc1; oacc[j][3] *= sc1;
        }
        __syncwarp();
        __syncthreads();                    // all warps done with K tile

        if (kt + 1 < nkt)
            fl_load_qk(sb, SKH, SKL, FK, g_Kh, g_Kl, (qkb + (size_t)(kt + 1) * FK) * DTOT, tid);
        cp_commit();
        cp_wait_group<1>();                 // V(kt) ready
        __syncthreads();

        // ---- O += P V (split-3) ----
#pragma unroll
        for (int ks = 0; ks < 4; ++ks) {
            int arow = mw + ((jA & 1) << 3) + rA;
            int achk = ks * 2 + (jA >> 1);
            uint32_t aoff = (uint32_t)(arow * 128 + ((achk ^ (arow & 7)) << 4));
            uint32_t pah[4], pal[4];
            ldm_x4(pah, sb + SPH + aoff);
            ldm_x4(pal, sb + SPL + aoff);
            int key = ks * 16 + (lane & 15);
#pragma unroll
            for (int p = 0; p < 8; ++p) {
                int dch = p * 2 + (lane >> 4);
                uint32_t voff = (uint32_t)(key * 256 + ((dch ^ (key & 7)) << 4));
                uint32_t th[4], tl[4];
                ldm_x4_t(th, sb + SVH + voff);
                ldm_x4_t(tl, sb + SVL + voff);
                mma_bf16(oacc[2 * p], pah, th);
                mma_bf16(oacc[2 * p], pal, th);
                mma_bf16(oacc[2 * p], pah, tl);
                mma_bf16(oacc[2 * p + 1], pah, th + 2);
                mma_bf16(oacc[2 * p + 1], pal, th + 2);
                mma_bf16(oacc[2 * p + 1], pah, tl + 2);
            }
        }
        __syncthreads();                    // all warps done with V tile

        if (kt + 1 < nkt)
            fl_load_v(sb, g_Vh, g_Vl, (qkb + (size_t)(kt + 1) * FK) * DHs, tid);
        cp_commit();
    }

    // ---- epilogue: normalize, split to bf16 hi/lo, write (B,L,D) ----
    float inv0 = 1.0f / l0, inv1 = 1.0f / l1;
    size_t ob0 = ((size_t)(b * Lsz + gr0)) * Dsz + h * DHs;
    size_t ob1 = ((size_t)(b * Lsz + gr0 + 8)) * Dsz + h * DHs;
#pragma unroll
    for (int j = 0; j < 16; ++j) {
        int d = j * 8 + ((lane & 3) << 1);
        float v0 = oacc[j][0] * inv0, v1 = oacc[j][1] * inv0;
        __nv_bfloat162 h2, l2;
        h2.x = __float2bfloat16(v0); h2.y = __float2bfloat16(v1);
        l2.x = __float2bfloat16(v0 - __bfloat162float(h2.x));
        l2.y = __float2bfloat16(v1 - __bfloat162float(h2.y));
        *(__nv_bfloat162*)&g_aoh[ob0 + d] = h2;
        *(__nv_bfloat162*)&g_aol[ob0 + d] = l2;
        float v2 = oacc[j][2] * inv1, v3 = oacc[j][3] * inv1;
        h2.x = __float2bfloat16(v2); h2.y = __float2bfloat16(v3);
        l2.x = __float2bfloat16(v2 - __bfloat162float(h2.x));
        l2.y = __float2bfloat16(v3 - __bfloat162float(h2.y));
        *(__nv_bfloat162*)&g_aoh[ob1 + d] = h2;
        *(__nv_bfloat162*)&g_aol[ob1 + d] = l2;
    }
}

// ---------------- launcher ----------------
extern "C" void kernel_launch(void* const* d_in, const int* in_sizes, int n_in,
                              void* d_out, int out_size) {
    const float* x     = (const float*)d_in[0];
    const float* W_DKV = (const float*)d_in[1];
    const float* W_UK  = (const float*)d_in[2];
    const float* W_UV  = (const float*)d_in[3];
    const float* W_DQ  = (const float*)d_in[4];
    const float* W_UQ  = (const float*)d_in[5];
    const float* W_QR  = (const float*)d_in[6];
    const float* W_KR  = (const float*)d_in[7];
    const float* W_O   = (const float*)d_in[8];
    const float* s_qk  = (const float*)d_in[9];
    float* out = (float*)d_out;

    float *kc, *vt, *qc, *qr, *kr2;
    cudaGetSymbolAddress((void**)&kc,  g_kc);
    cudaGetSymbolAddress((void**)&vt,  g_vt);
    cudaGetSymbolAddress((void**)&qc,  g_qc);
    cudaGetSymbolAddress((void**)&qr,  g_qr);
    cudaGetSymbolAddress((void**)&kr2, g_kr2);

    __nv_bfloat16 *xh, *xl, *ckvh, *ckvl, *cqh, *cql, *aoh, *aol;
    __nv_bfloat16 *wdkvh, *wdkvl, *wdqh, *wdql, *wukh, *wukl, *wuvh, *wuvl;
    __nv_bfloat16 *wuqh, *wuql, *wqrh, *wqrl, *wkrh, *wkrl, *woh, *wol;
    cudaGetSymbolAddress((void**)&xh, g_xh);     cudaGetSymbolAddress((void**)&xl, g_xl);
    cudaGetSymbolAddress((void**)&ckvh, g_ckvh); cudaGetSymbolAddress((void**)&ckvl, g_ckvl);
    cudaGetSymbolAddress((void**)&cqh, g_cqh);   cudaGetSymbolAddress((void**)&cql, g_cql);
    cudaGetSymbolAddress((void**)&aoh, g_aoh);   cudaGetSymbolAddress((void**)&aol, g_aol);
    cudaGetSymbolAddress((void**)&wdkvh, g_wdkvh); cudaGetSymbolAddress((void**)&wdkvl, g_wdkvl);
    cudaGetSymbolAddress((void**)&wdqh, g_wdqh);   cudaGetSymbolAddress((void**)&wdql, g_wdql);
    cudaGetSymbolAddress((void**)&wukh, g_wukh);   cudaGetSymbolAddress((void**)&wukl, g_wukl);
    cudaGetSymbolAddress((void**)&wuvh, g_wuvh);   cudaGetSymbolAddress((void**)&wuvl, g_wuvl);
    cudaGetSymbolAddress((void**)&wuqh, g_wuqh);   cudaGetSymbolAddress((void**)&wuql, g_wuql);
    cudaGetSymbolAddress((void**)&wqrh, g_wqrh);   cudaGetSymbolAddress((void**)&wqrl, g_wqrl);
    cudaGetSymbolAddress((void**)&wkrh, g_wkrh);   cudaGetSymbolAddress((void**)&wkrl, g_wkrl);
    cudaGetSymbolAddress((void**)&woh, g_woh);     cudaGetSymbolAddress((void**)&wol, g_wol);

    cudaFuncSetAttribute(mm_mma_kernel, cudaFuncAttributeMaxDynamicSharedMemorySize, MM_SMEM);
    cudaFuncSetAttribute(flashmma_kernel, cudaFuncAttributeMaxDynamicSharedMemorySize, FLASH_SMEM);

    dim3 tsb(32, 8);
    tsplit_kernel<<<dim3(DCs/32, Dsz/32), tsb>>>(W_DKV, wdkvh, wdkvl, Dsz, DCs);
    tsplit_kernel<<<dim3(DCs/32, Dsz/32), tsb>>>(W_DQ,  wdqh,  wdql,  Dsz, DCs);
    tsplit_kernel<<<dim3(Dsz/32, DCs/32), tsb>>>(W_UK,  wukh,  wukl,  DCs, Dsz);
    tsplit_kernel<<<dim3(Dsz/32, DCs/32), tsb>>>(W_UV,  wuvh,  wuvl,  DCs, Dsz);
    tsplit_kernel<<<dim3(Dsz/32, DCs/32), tsb>>>(W_UQ,  wuqh,  wuql,  DCs, Dsz);
    tsplit_kernel<<<dim3((NHs*DHRs)/32, DCs/32), tsb>>>(W_QR, wqrh, wqrl, DCs, NHs*DHRs);
    tsplit_kernel<<<dim3(DHRs/32, Dsz/32), tsb>>>(W_KR, wkrh, wkrl, Dsz, DHRs);  // rows 64..127 stay zero
    tsplit_kernel<<<dim3(Dsz/32, Dsz/32), tsb>>>(W_O,   woh,   wol,   Dsz, Dsz);

    { int n = Msz * Dsz; split_kernel<<<(n + 255) / 256, 256>>>(x, xh, xl, n); }

    // down-projections -> bf16 hi/lo directly; KR via padded N=128 GEMM
    mm_mma_kernel<<<dim3(DCs/128, Msz/128), 256, MM_SMEM>>>(xh, xl, wdkvh, wdkvl, nullptr, ckvh, ckvl, Msz, DCs, Dsz);
    mm_mma_kernel<<<dim3(DCs/128, Msz/128), 256, MM_SMEM>>>(xh, xl, wdqh,  wdql,  nullptr, cqh,  cql,  Msz, DCs, Dsz);
    mm_mma_kernel<<<dim3(1, Msz/128), 256, MM_SMEM>>>(xh, xl, wkrh, wkrl, kr2, nullptr, nullptr, Msz, 128, Dsz);

    // up-projections -> fp32 (consumed by assemble)
    mm_mma_kernel<<<dim3(Dsz/128, Msz/128), 256, MM_SMEM>>>(ckvh, ckvl, wukh, wukl, kc, nullptr, nullptr, Msz, Dsz, DCs);
    mm_mma_kernel<<<dim3(Dsz/128, Msz/128), 256, MM_SMEM>>>(ckvh, ckvl, wuvh, wuvl, vt, nullptr, nullptr, Msz, Dsz, DCs);
    mm_mma_kernel<<<dim3(Dsz/128, Msz/128), 256, MM_SMEM>>>(cqh,  cql,  wuqh, wuql, qc, nullptr, nullptr, Msz, Dsz, DCs);
    mm_mma_kernel<<<dim3((NHs*DHRs)/128, Msz/128), 256, MM_SMEM>>>(cqh, cql, wqrh, wqrl, qr, nullptr, nullptr, Msz, NHs*DHRs, DCs);

    // RoPE + concat + normalize -> bf16 hi/lo Q,K,V
    assemble_kernel<<<Msz, 512>>>(s_qk);

    // tensor-core causal flash attention -> aoh/aol
    flashmma_kernel<<<dim3(Lsz / FQ, NHs, Bsz), 256, FLASH_SMEM>>>();

    // output projection
    mm_mma_kernel<<<dim3(Dsz/128, Msz/128), 256, MM_SMEM>>>(aoh, aol, woh, wol, out, nullptr, nullptr, Msz, Dsz, Dsz);
}

// round 8
// speedup vs baseline: 4.2901x; 1.0560x over previous
#include <cuda_runtime.h>
#include <cuda_bf16.h>
#include <math.h>
#include <stdint.h>

// ---------------- problem constants ----------------
#define Bsz   4
#define Lsz   2048
#define Dsz   2048
#define NHs   16
#define DHs   128
#define DHRs  64
#define DCs   1024
#define DTOT  (DHs + DHRs)     // 192
#define Msz   (Bsz * Lsz)      // 8192

// ---------------- fp32 scratch ----------------
__device__ float g_kc [Msz * Dsz];
__device__ float g_vt [Msz * Dsz];
__device__ float g_qc [Msz * Dsz];
__device__ float g_qr [Msz * (NHs * DHRs)];
__device__ float g_kr2[Msz * 128];            // padded KR output (cols 64..127 unused)

// ---------------- bf16 split scratch ----------------
__device__ __align__(256) __nv_bfloat16 g_xh [Msz * Dsz];
__device__ __align__(256) __nv_bfloat16 g_xl [Msz * Dsz];
__device__ __align__(256) __nv_bfloat16 g_ckvh[Msz * DCs];
__device__ __align__(256) __nv_bfloat16 g_ckvl[Msz * DCs];
__device__ __align__(256) __nv_bfloat16 g_cqh [Msz * DCs];
__device__ __align__(256) __nv_bfloat16 g_cql [Msz * DCs];
__device__ __align__(256) __nv_bfloat16 g_aoh [Msz * Dsz];
__device__ __align__(256) __nv_bfloat16 g_aol [Msz * Dsz];
// attention operands, hi/lo
__device__ __align__(256) __nv_bfloat16 g_Qh [Bsz*NHs*Lsz*DTOT], g_Ql [Bsz*NHs*Lsz*DTOT];
__device__ __align__(256) __nv_bfloat16 g_Kh [Bsz*NHs*Lsz*DTOT], g_Kl [Bsz*NHs*Lsz*DTOT];
__device__ __align__(256) __nv_bfloat16 g_Vh [Bsz*NHs*Lsz*DHs],  g_Vl [Bsz*NHs*Lsz*DHs];
// stacked transposed weights [N x K] hi/lo  (zero-init guaranteed for pad rows)
__device__ __align__(256) __nv_bfloat16 g_wdkvh[DCs * Dsz],        g_wdkvl[DCs * Dsz];
__device__ __align__(256) __nv_bfloat16 g_wdqkrh[(DCs+128) * Dsz], g_wdqkrl[(DCs+128) * Dsz];
__device__ __align__(256) __nv_bfloat16 g_wukvh[(2*Dsz) * DCs],    g_wukvl[(2*Dsz) * DCs];
__device__ __align__(256) __nv_bfloat16 g_wuqrh[(Dsz+NHs*DHRs) * DCs], g_wuqrl[(Dsz+NHs*DHRs) * DCs];
__device__ __align__(256) __nv_bfloat16 g_woh  [Dsz * Dsz],        g_wol  [Dsz * Dsz];

// ---------------- PTX helpers (baseline ISA only) ----------------
__device__ __forceinline__ uint32_t smem_u32(const void* p) {
    uint32_t a;
    asm("{ .reg .u64 t; cvta.to.shared.u64 t, %1; cvt.u32.u64 %0, t; }" : "=r"(a) : "l"(p));
    return a;
}
__device__ __forceinline__ void cpa16(uint32_t s, const void* g) {
    asm volatile("cp.async.cg.shared.global [%0], [%1], 16;" :: "r"(s), "l"(g) : "memory");
}
__device__ __forceinline__ void cp_commit() {
    asm volatile("cp.async.commit_group;" ::: "memory");
}
template <int N> __device__ __forceinline__ void cp_wait_group() {
    asm volatile("cp.async.wait_group %0;" :: "n"(N) : "memory");
}
__device__ __forceinline__ void ldm_x4(uint32_t* r, uint32_t addr) {
    asm volatile("ldmatrix.sync.aligned.m8n8.x4.shared.b16 {%0,%1,%2,%3}, [%4];"
                 : "=r"(r[0]), "=r"(r[1]), "=r"(r[2]), "=r"(r[3]) : "r"(addr));
}
__device__ __forceinline__ void ldm_x4_t(uint32_t* r, uint32_t addr) {
    asm volatile("ldmatrix.sync.aligned.m8n8.x4.trans.shared.b16 {%0,%1,%2,%3}, [%4];"
                 : "=r"(r[0]), "=r"(r[1]), "=r"(r[2]), "=r"(r[3]) : "r"(addr));
}
__device__ __forceinline__ void mma_bf16(float* c, const uint32_t* a, const uint32_t* b) {
    asm volatile(
        "mma.sync.aligned.m16n8k16.row.col.f32.bf16.bf16.f32 "
        "{%0,%1,%2,%3}, {%4,%5,%6,%7}, {%8,%9}, {%0,%1,%2,%3};"
        : "+f"(c[0]), "+f"(c[1]), "+f"(c[2]), "+f"(c[3])
        : "r"(a[0]), "r"(a[1]), "r"(a[2]), "r"(a[3]), "r"(b[0]), "r"(b[1]));
}

// ---------------- split / transpose-split conversions ----------------
__global__ void split_kernel(const float* __restrict__ src,
                             __nv_bfloat16* __restrict__ hi,
                             __nv_bfloat16* __restrict__ lo, int n) {
    int i = (blockIdx.x * 256 + threadIdx.x) * 4;
    if (i < n) {
        float4 v = *(const float4*)&src[i];
        __nv_bfloat162 h0, h1, l0, l1;
        h0.x = __float2bfloat16(v.x); h0.y = __float2bfloat16(v.y);
        h1.x = __float2bfloat16(v.z); h1.y = __float2bfloat16(v.w);
        l0.x = __float2bfloat16(v.x - __bfloat162float(h0.x));
        l0.y = __float2bfloat16(v.y - __bfloat162float(h0.y));
        l1.x = __float2bfloat16(v.z - __bfloat162float(h1.x));
        l1.y = __float2bfloat16(v.w - __bfloat162float(h1.y));
        *(__nv_bfloat162*)&hi[i]     = h0;
        *(__nv_bfloat162*)&hi[i + 2] = h1;
        *(__nv_bfloat162*)&lo[i]     = l0;
        *(__nv_bfloat162*)&lo[i + 2] = l1;
    }
}

// W[K x N] row-major -> Th/Tl [N x K] row-major bf16 hi/lo
__global__ void tsplit_kernel(const float* __restrict__ W,
                              __nv_bfloat16* __restrict__ Th,
                              __nv_bfloat16* __restrict__ Tl, int K, int N) {
    __shared__ float t[32][33];
    int kb = blockIdx.y * 32, nb = blockIdx.x * 32;
    int tx = threadIdx.x, ty = threadIdx.y;    // (32, 8)
#pragma unroll
    for (int r = 0; r < 32; r += 8)
        t[ty + r][tx] = W[(size_t)(kb + ty + r) * N + nb + tx];
    __syncthreads();
#pragma unroll
    for (int r = 0; r < 32; r += 8) {
        float x = t[tx][ty + r];
        __nv_bfloat16 h = __float2bfloat16(x);
        float res = x - __bfloat162float(h);
        size_t o = (size_t)(nb + ty + r) * K + kb + tx;
        Th[o] = h;
        Tl[o] = __float2bfloat16(res);
    }
}

// ---------------- mma.sync bf16 split-3 GEMM (3-stage, region-split epilogue) ----------------
#define MMS_A_H 0
#define MMS_A_L 8192
#define MMS_B_H 16384
#define MMS_B_L 24576
#define MMS_STAGE 32768
#define MM_SMEM (3 * MMS_STAGE)

__device__ __forceinline__ void mm_load_stage(
    uint32_t sbase,
    const __nv_bfloat16* __restrict__ Ah, const __nv_bfloat16* __restrict__ Al,
    const __nv_bfloat16* __restrict__ Bh, const __nv_bfloat16* __restrict__ Bl,
    int m0, int n0, int k0, int Kd, int tid)
{
#pragma unroll
    for (int t = 0; t < 2; ++t) {
        int idx = tid + t * 256;
        int row = idx >> 2;
        int c   = idx & 3;
        uint32_t so = (uint32_t)(row * 64 + ((c ^ (row & 3)) << 4));
        size_t ga = (size_t)(m0 + row) * Kd + k0 + c * 8;
        size_t gb = (size_t)(n0 + row) * Kd + k0 + c * 8;
        cpa16(sbase + MMS_A_H + so, Ah + ga);
        cpa16(sbase + MMS_A_L + so, Al + ga);
        cpa16(sbase + MMS_B_H + so, Bh + gb);
        cpa16(sbase + MMS_B_L + so, Bl + gb);
    }
}

// Output regions: cols [0, Nsplit): Cf (fp32, stride Nsplit) if non-null else Ch/Cl bf16 pair (stride Nsplit).
//                 cols [Nsplit, Nd): Cf2 (fp32, stride Nd-Nsplit, col -= Nsplit).
__global__ void __launch_bounds__(256, 1)
mm_mma_kernel(const __nv_bfloat16* __restrict__ Ahg, const __nv_bfloat16* __restrict__ Alg,
              const __nv_bfloat16* __restrict__ Bhg, const __nv_bfloat16* __restrict__ Blg,
              float* __restrict__ Cf,
              __nv_bfloat16* __restrict__ Ch, __nv_bfloat16* __restrict__ Cl,
              float* __restrict__ Cf2,
              int Md, int Nd, int Kd, int Nsplit) {
    extern __shared__ __align__(1024) char smem[];
    const uint32_t sb = smem_u32(smem);
    const int tid = threadIdx.x, wid = tid >> 5, lane = tid & 31;
    const int m0 = blockIdx.y * 128, n0 = blockIdx.x * 128;
    const int mw = (wid & 3) * 32;
    const int nw = (wid >> 2) * 64;

    float acc[2][8][4];
#pragma unroll
    for (int i = 0; i < 2; ++i)
#pragma unroll
        for (int j = 0; j < 8; ++j)
#pragma unroll
            for (int q = 0; q < 4; ++q) acc[i][j][q] = 0.f;

    const int nk = Kd >> 5;
    mm_load_stage(sb + 0 * MMS_STAGE, Ahg, Alg, Bhg, Blg, m0, n0, 0, Kd, tid);
    cp_commit();
    mm_load_stage(sb + 1 * MMS_STAGE, Ahg, Alg, Bhg, Blg, m0, n0, 32, Kd, tid);
    cp_commit();

    const int jA = lane >> 3, rA = lane & 7;

    int sidx = 0;                          // stage of iteration it
    for (int it = 0; it < nk; ++it) {
        cp_wait_group<1>();
        __syncthreads();

        if (it + 2 < nk) {
            int ps = sidx + 2; if (ps >= 3) ps -= 3;
            mm_load_stage(sb + ps * MMS_STAGE, Ahg, Alg, Bhg, Blg,
                          m0, n0, (it + 2) << 5, Kd, tid);
        }
        cp_commit();

        const uint32_t stg = sb + sidx * MMS_STAGE;

#pragma unroll
        for (int ks = 0; ks < 2; ++ks) {
            uint32_t ah[2][4], al[2][4];
#pragma unroll
            for (int i = 0; i < 2; ++i) {
                int m = mw + i * 16 + ((jA & 1) << 3) + rA;
                int c = (ks << 1) + (jA >> 1);
                uint32_t off = (uint32_t)(m * 64 + ((c ^ (m & 3)) << 4));
                ldm_x4(ah[i], stg + MMS_A_H + off);
                ldm_x4(al[i], stg + MMS_A_L + off);
            }
            uint32_t bh[8][2], bl[8][2];
#pragma unroll
            for (int p = 0; p < 4; ++p) {
                int n = nw + p * 16 + ((jA >> 1) << 3) + rA;
                int c = (ks << 1) + (jA & 1);
                uint32_t off = (uint32_t)(n * 64 + ((c ^ (n & 3)) << 4));
                uint32_t tmp[4];
                ldm_x4(tmp, stg + MMS_B_H + off);
                bh[2 * p][0] = tmp[0]; bh[2 * p][1] = tmp[1];
                bh[2 * p + 1][0] = tmp[2]; bh[2 * p + 1][1] = tmp[3];
                ldm_x4(tmp, stg + MMS_B_L + off);
                bl[2 * p][0] = tmp[0]; bl[2 * p][1] = tmp[1];
                bl[2 * p + 1][0] = tmp[2]; bl[2 * p + 1][1] = tmp[3];
            }
#pragma unroll
            for (int i = 0; i < 2; ++i)
#pragma unroll
                for (int j = 0; j < 8; ++j) {
                    mma_bf16(acc[i][j], ah[i], bh[j]);
                    mma_bf16(acc[i][j], al[i], bh[j]);
                    mma_bf16(acc[i][j], ah[i], bl[j]);
                }
        }
        if (++sidx == 3) sidx = 0;
    }

    // ---- region-split epilogue ----
    const bool regB = (n0 >= Nsplit);
#pragma unroll
    for (int i = 0; i < 2; ++i) {
        int row = m0 + mw + i * 16 + (lane >> 2);
#pragma unroll
        for (int j = 0; j < 8; ++j) {
            int col = n0 + nw + j * 8 + ((lane & 3) << 1);
            if (regB) {
                int st = Nd - Nsplit, cc = col - Nsplit;
                *(float2*)&Cf2[(size_t)row * st + cc]       = make_float2(acc[i][j][0], acc[i][j][1]);
                *(float2*)&Cf2[(size_t)(row + 8) * st + cc] = make_float2(acc[i][j][2], acc[i][j][3]);
            } else if (Cf) {
                *(float2*)&Cf[(size_t)row * Nsplit + col]       = make_float2(acc[i][j][0], acc[i][j][1]);
                *(float2*)&Cf[(size_t)(row + 8) * Nsplit + col] = make_float2(acc[i][j][2], acc[i][j][3]);
            } else {
#pragma unroll
                for (int hh = 0; hh < 2; ++hh) {
                    float v0 = acc[i][j][2 * hh], v1 = acc[i][j][2 * hh + 1];
                    __nv_bfloat162 h2, l2;
                    h2.x = __float2bfloat16(v0); h2.y = __float2bfloat16(v1);
                    l2.x = __float2bfloat16(v0 - __bfloat162float(h2.x));
                    l2.y = __float2bfloat16(v1 - __bfloat162float(h2.y));
                    size_t o = (size_t)(row + 8 * hh) * Nsplit + col;
                    *(__nv_bfloat162*)&Ch[o] = h2;
                    *(__nv_bfloat162*)&Cl[o] = l2;
                }
            }
        }
    }
}

// ---------------- assemble: RoPE + concat + normalize -> bf16 hi/lo Q,K,V ----------------
#define LOG2_ROPE_BASE 13.287712379549449f

__global__ void __launch_bounds__(512)
assemble_kernel(const float* __restrict__ s_qk_ptr) {
    const int bl = blockIdx.x;
    const int b  = bl / Lsz;
    const int l  = bl % Lsz;
    const int w    = threadIdx.x >> 5;
    const int lane = threadIdx.x & 31;
    const float s_qk = *s_qk_ptr;

    float qv[3][2], kv[3][2];
    float ssq = 0.f, ssk = 0.f;

#pragma unroll
    for (int j = 0; j < 3; ++j) {
        if (j < 2) {
            int d = j * 64 + lane * 2;
            float2 qq = *(const float2*)&g_qc[(size_t)bl * Dsz + w * DHs + d];
            float2 kk = *(const float2*)&g_kc[(size_t)bl * Dsz + w * DHs + d];
            qv[j][0] = qq.x; qv[j][1] = qq.y;
            kv[j][0] = kk.x; kv[j][1] = kk.y;
        } else {
            int dr = lane * 2;               // 0..62, even; pair stays on one side of 32
            const float* qrp = &g_qr[(size_t)bl * (NHs * DHRs) + w * DHRs];
            const float* krp = &g_kr2[(size_t)bl * 128];
            float2 q1 = *(const float2*)&qrp[dr];
            float2 k1 = *(const float2*)&krp[dr];
            float2 q2, k2;
            float sgn;
            if (dr < 32) {
                q2 = *(const float2*)&qrp[dr + 32];
                k2 = *(const float2*)&krp[dr + 32];
                sgn = -1.f;
            } else {
                q2 = *(const float2*)&qrp[dr - 32];
                k2 = *(const float2*)&krp[dr - 32];
                sgn = 1.f;
            }
#pragma unroll
            for (int e = 0; e < 2; ++e) {
                int i = (dr + e) & 31;
                float invf = exp2f(-(float)i * (LOG2_ROPE_BASE / 32.0f));
                float ang  = (float)l * invf;
                float sn, cs;
                sincosf(ang, &sn, &cs);
                float x1 = e ? q1.y : q1.x;
                float x2 = sgn * (e ? q2.y : q2.x);
                float y1 = e ? k1.y : k1.x;
                float y2 = sgn * (e ? k2.y : k2.x);
                qv[2][e] = x1 * cs + x2 * sn;
                kv[2][e] = y1 * cs + y2 * sn;
            }
        }
        ssq += qv[j][0] * qv[j][0] + qv[j][1] * qv[j][1];
        ssk += kv[j][0] * kv[j][0] + kv[j][1] * kv[j][1];
    }
#pragma unroll
    for (int o = 16; o; o >>= 1) {
        ssq += __shfl_xor_sync(0xffffffffu, ssq, o);
        ssk += __shfl_xor_sync(0xffffffffu, ssk, o);
    }
    float qn = s_qk / fmaxf(sqrtf(ssq), 1e-12f);
    float kn = 1.0f / fmaxf(sqrtf(ssk), 1e-12f);

    size_t base = ((size_t)(b * NHs + w) * Lsz + l);
#pragma unroll
    for (int j = 0; j < 3; ++j) {
        int d = j * 64 + lane * 2;
        float q0 = qv[j][0] * qn, q1 = qv[j][1] * qn;
        float k0 = kv[j][0] * kn, k1 = kv[j][1] * kn;
        __nv_bfloat162 h2, l2;
        h2.x = __float2bfloat16(q0); h2.y = __float2bfloat16(q1);
        l2.x = __float2bfloat16(q0 - __bfloat162float(h2.x));
        l2.y = __float2bfloat16(q1 - __bfloat162float(h2.y));
        *(__nv_bfloat162*)&g_Qh[base * DTOT + d] = h2;
        *(__nv_bfloat162*)&g_Ql[base * DTOT + d] = l2;
        h2.x = __float2bfloat16(k0); h2.y = __float2bfloat16(k1);
        l2.x = __float2bfloat16(k0 - __bfloat162float(h2.x));
        l2.y = __float2bfloat16(k1 - __bfloat162float(h2.y));
        *(__nv_bfloat162*)&g_Kh[base * DTOT + d] = h2;
        *(__nv_bfloat162*)&g_Kl[base * DTOT + d] = l2;
    }
#pragma unroll
    for (int dd = 0; dd < 2; ++dd) {
        int d = dd * 64 + lane * 2;
        float2 vv = *(const float2*)&g_vt[(size_t)bl * Dsz + w * DHs + d];
        __nv_bfloat162 h2, l2;
        h2.x = __float2bfloat16(vv.x); h2.y = __float2bfloat16(vv.y);
        l2.x = __float2bfloat16(vv.x - __bfloat162float(h2.x));
        l2.y = __float2bfloat16(vv.y - __bfloat162float(h2.y));
        *(__nv_bfloat162*)&g_Vh[base * DHs + d] = h2;
        *(__nv_bfloat162*)&g_Vl[base * DHs + d] = l2;
    }
}

// ---------------- tensor-core causal flash attention (split-3 bf16) ----------------
#define FQ 128
#define FK 64
#define SQH 0
#define SQL (SQH + FQ*384)
#define SKH (SQL + FQ*384)
#define SKL (SKH + FK*384)
#define SVH (SKL + FK*384)
#define SVL (SVH + FK*256)
#define SPH (SVL + FK*256)
#define SPL (SPH + FQ*128)
#define FLASH_SMEM (SPL + FQ*128)   // 212992 bytes

__device__ __forceinline__ void fl_load_qk(
    uint32_t sb, uint32_t offH, uint32_t offL, int rows,
    const __nv_bfloat16* __restrict__ Gh, const __nv_bfloat16* __restrict__ Gl,
    size_t gbase, int tid)
{
    for (int idx = tid; idx < rows * 24; idx += 256) {
        int r = idx / 24, c = idx % 24;
        uint32_t so = (uint32_t)(r * 384 + ((c ^ (r & 7)) << 4));
        size_t g = gbase + (size_t)r * DTOT + c * 8;
        cpa16(sb + offH + so, Gh + g);
        cpa16(sb + offL + so, Gl + g);
    }
}
__device__ __forceinline__ void fl_load_v(
    uint32_t sb, const __nv_bfloat16* __restrict__ Gh, const __nv_bfloat16* __restrict__ Gl,
    size_t gbase, int tid)
{
    for (int idx = tid; idx < FK * 16; idx += 256) {
        int r = idx >> 4, c = idx & 15;
        uint32_t so = (uint32_t)(r * 256 + ((c ^ (r & 7)) << 4));
        size_t g = gbase + (size_t)r * DHs + c * 8;
        cpa16(sb + SVH + so, Gh + g);
        cpa16(sb + SVL + so, Gl + g);
    }
}

__global__ void __launch_bounds__(256, 1)
flashmma_kernel() {
    extern __shared__ __align__(1024) char sm[];
    const uint32_t sb = smem_u32(sm);
    const int tid = threadIdx.x, w = tid >> 5, lane = tid & 31;
    const int qt = (int)(gridDim.x - 1u - blockIdx.x);
    const int h = blockIdx.y, b = blockIdx.z;
    const int q0 = qt * FQ;
    const int mw = w * 16;
    const int jA = lane >> 3, rA = lane & 7;

    const size_t qkb = (size_t)(b * NHs + h) * Lsz;
    fl_load_qk(sb, SQH, SQL, FQ, g_Qh, g_Ql, (qkb + q0) * DTOT, tid);
    cp_commit();
    fl_load_qk(sb, SKH, SKL, FK, g_Kh, g_Kl, qkb * DTOT, tid);
    cp_commit();
    fl_load_v(sb, g_Vh, g_Vl, qkb * DHs, tid);
    cp_commit();

    float oacc[16][4];
#pragma unroll
    for (int j = 0; j < 16; ++j)
#pragma unroll
        for (int q = 0; q < 4; ++q) oacc[j][q] = 0.f;
    float m0 = -1e30f, m1 = -1e30f, l0 = 0.f, l1 = 0.f;

    const int nkt = 2 * qt + 2;
    const int r0loc = mw + (lane >> 2);
    const int gr0 = q0 + r0loc;

    for (int kt = 0; kt < nkt; ++kt) {
        cp_wait_group<1>();
        __syncthreads();

        // ---- S = Q K^T (split-3) ----
        float sacc[8][4];
#pragma unroll
        for (int j = 0; j < 8; ++j)
#pragma unroll
            for (int q = 0; q < 4; ++q) sacc[j][q] = 0.f;

#pragma unroll
        for (int ks = 0; ks < 12; ++ks) {
            int arow = mw + ((jA & 1) << 3) + rA;
            int achk = ks * 2 + (jA >> 1);
            uint32_t aoff = (uint32_t)(arow * 384 + ((achk ^ (arow & 7)) << 4));
            uint32_t ah[4], al[4];
            ldm_x4(ah, sb + SQH + aoff);
            ldm_x4(al, sb + SQL + aoff);
            uint32_t bh[8][2], bl[8][2];
#pragma unroll
            for (int p = 0; p < 4; ++p) {
                int brow = p * 16 + ((jA >> 1) << 3) + rA;
                int bchk = ks * 2 + (jA & 1);
                uint32_t boff = (uint32_t)(brow * 384 + ((bchk ^ (brow & 7)) << 4));
                uint32_t tmp[4];
                ldm_x4(tmp, sb + SKH + boff);
                bh[2 * p][0] = tmp[0]; bh[2 * p][1] = tmp[1];
                bh[2 * p + 1][0] = tmp[2]; bh[2 * p + 1][1] = tmp[3];
                ldm_x4(tmp, sb + SKL + boff);
                bl[2 * p][0] = tmp[0]; bl[2 * p][1] = tmp[1];
                bl[2 * p + 1][0] = tmp[2]; bl[2 * p + 1][1] = tmp[3];
            }
#pragma unroll
            for (int j = 0; j < 8; ++j) {
                mma_bf16(sacc[j], ah, bh[j]);
                mma_bf16(sacc[j], al, bh[j]);
                mma_bf16(sacc[j], ah, bl[j]);
            }
        }

        // ---- causal mask (last two k-tiles only) ----
        if (kt >= 2 * qt) {
            int k0 = kt * FK;
#pragma unroll
            for (int j = 0; j < 8; ++j) {
                int col = k0 + j * 8 + ((lane & 3) << 1);
                if (col > gr0)     sacc[j][0] = -1e30f;
                if (col + 1 > gr0) sacc[j][1] = -1e30f;
                if (col > gr0 + 8)     sacc[j][2] = -1e30f;
                if (col + 1 > gr0 + 8) sacc[j][3] = -1e30f;
            }
        }

        // ---- online softmax ----
        float mx0 = -1e30f, mx1 = -1e30f;
#pragma unroll
        for (int j = 0; j < 8; ++j) {
            mx0 = fmaxf(mx0, fmaxf(sacc[j][0], sacc[j][1]));
            mx1 = fmaxf(mx1, fmaxf(sacc[j][2], sacc[j][3]));
        }
#pragma unroll
        for (int o = 1; o <= 2; o <<= 1) {
            mx0 = fmaxf(mx0, __shfl_xor_sync(0xffffffffu, mx0, o));
            mx1 = fmaxf(mx1, __shfl_xor_sync(0xffffffffu, mx1, o));
        }
        float mn0 = fmaxf(m0, mx0), mn1 = fmaxf(m1, mx1);
        float sc0 = __expf(m0 - mn0), sc1 = __expf(m1 - mn1);
        m0 = mn0; m1 = mn1;

        float rs0 = 0.f, rs1 = 0.f;
        const int pr0 = r0loc, pr1 = r0loc + 8;
        const uint32_t pbyte = (uint32_t)((lane & 3) << 2);
#pragma unroll
        for (int j = 0; j < 8; ++j) {
            float p0 = __expf(sacc[j][0] - mn0);
            float p1 = __expf(sacc[j][1] - mn0);
            float p2 = __expf(sacc[j][2] - mn1);
            float p3 = __expf(sacc[j][3] - mn1);
            rs0 += p0 + p1; rs1 += p2 + p3;
            __nv_bfloat162 h2, l2;
            h2.x = __float2bfloat16(p0); h2.y = __float2bfloat16(p1);
            l2.x = __float2bfloat16(p0 - __bfloat162float(h2.x));
            l2.y = __float2bfloat16(p1 - __bfloat162float(h2.y));
            uint32_t off0 = (uint32_t)(pr0 * 128 + ((j ^ (pr0 & 7)) << 4)) + pbyte;
            *(__nv_bfloat162*)(sm + SPH + off0) = h2;
            *(__nv_bfloat162*)(sm + SPL + off0) = l2;
            h2.x = __float2bfloat16(p2); h2.y = __float2bfloat16(p3);
            l2.x = __float2bfloat16(p2 - __bfloat162float(h2.x));
            l2.y = __float2bfloat16(p3 - __bfloat162float(h2.y));
            uint32_t off1 = (uint32_t)(pr1 * 128 + ((j ^ (pr1 & 7)) << 4)) + pbyte;
            *(__nv_bfloat162*)(sm + SPH + off1) = h2;
            *(__nv_bfloat162*)(sm + SPL + off1) = l2;
        }
#pragma unroll
        for (int o = 1; o <= 2; o <<= 1) {
            rs0 += __shfl_xor_sync(0xffffffffu, rs0, o);
            rs1 += __shfl_xor_sync(0xffffffffu, rs1, o);
        }
        l0 = l0 * sc0 + rs0;
        l1 = l1 * sc1 + rs1;
#pragma unroll
        for (int j = 0; j < 16; ++j) {
            oacc[j][0] *= sc0; oacc[j][1] *= sc0;
            oacc[j][2] *= sc1; oacc[j][3] *= sc1;
        }
        __syncwarp();
        __syncthreads();                    // all warps done with K tile

        if (kt + 1 < nkt)
            fl_load_qk(sb, SKH, SKL, FK, g_Kh, g_Kl, (qkb + (size_t)(kt + 1) * FK) * DTOT, tid);
        cp_commit();
        cp_wait_group<1>();                 // V(kt) ready
        __syncthreads();

        // ---- O += P V (split-3) ----
#pragma unroll
        for (int ks = 0; ks < 4; ++ks) {
            int arow = mw + ((jA & 1) << 3) + rA;
            int achk = ks * 2 + (jA >> 1);
            uint32_t aoff = (uint32_t)(arow * 128 + ((achk ^ (arow & 7)) << 4));
            uint32_t pah[4], pal[4];
            ldm_x4(pah, sb + SPH + aoff);
            ldm_x4(pal, sb + SPL + aoff);
            int key = ks * 16 + (lane & 15);
#pragma unroll
            for (int p = 0; p < 8; ++p) {
                int dch = p * 2 + (lane >> 4);
                uint32_t voff = (uint32_t)(key * 256 + ((dch ^ (key & 7)) << 4));
                uint32_t th[4], tl[4];
                ldm_x4_t(th, sb + SVH + voff);
                ldm_x4_t(tl, sb + SVL + voff);
                mma_bf16(oacc[2 * p], pah, th);
                mma_bf16(oacc[2 * p], pal, th);
                mma_bf16(oacc[2 * p], pah, tl);
                mma_bf16(oacc[2 * p + 1], pah, th + 2);
                mma_bf16(oacc[2 * p + 1], pal, th + 2);
                mma_bf16(oacc[2 * p + 1], pah, tl + 2);
            }
        }
        __syncthreads();                    // all warps done with V tile

        if (kt + 1 < nkt)
            fl_load_v(sb, g_Vh, g_Vl, (qkb + (size_t)(kt + 1) * FK) * DHs, tid);
        cp_commit();
    }

    // ---- epilogue ----
    float inv0 = 1.0f / l0, inv1 = 1.0f / l1;
    size_t ob0 = ((size_t)(b * Lsz + gr0)) * Dsz + h * DHs;
    size_t ob1 = ((size_t)(b * Lsz + gr0 + 8)) * Dsz + h * DHs;
#pragma unroll
    for (int j = 0; j < 16; ++j) {
        int d = j * 8 + ((lane & 3) << 1);
        float v0 = oacc[j][0] * inv0, v1 = oacc[j][1] * inv0;
        __nv_bfloat162 h2, l2;
        h2.x = __float2bfloat16(v0); h2.y = __float2bfloat16(v1);
        l2.x = __float2bfloat16(v0 - __bfloat162float(h2.x));
        l2.y = __float2bfloat16(v1 - __bfloat162float(h2.y));
        *(__nv_bfloat162*)&g_aoh[ob0 + d] = h2;
        *(__nv_bfloat162*)&g_aol[ob0 + d] = l2;
        float v2 = oacc[j][2] * inv1, v3 = oacc[j][3] * inv1;
        h2.x = __float2bfloat16(v2); h2.y = __float2bfloat16(v3);
        l2.x = __float2bfloat16(v2 - __bfloat162float(h2.x));
        l2.y = __float2bfloat16(v3 - __bfloat162float(h2.y));
        *(__nv_bfloat162*)&g_aoh[ob1 + d] = h2;
        *(__nv_bfloat162*)&g_aol[ob1 + d] = l2;
    }
}

// ---------------- launcher ----------------
extern "C" void kernel_launch(void* const* d_in, const int* in_sizes, int n_in,
                              void* d_out, int out_size) {
    const float* x     = (const float*)d_in[0];
    const float* W_DKV = (const float*)d_in[1];
    const float* W_UK  = (const float*)d_in[2];
    const float* W_UV  = (const float*)d_in[3];
    const float* W_DQ  = (const float*)d_in[4];
    const float* W_UQ  = (const float*)d_in[5];
    const float* W_QR  = (const float*)d_in[6];
    const float* W_KR  = (const float*)d_in[7];
    const float* W_O   = (const float*)d_in[8];
    const float* s_qk  = (const float*)d_in[9];
    float* out = (float*)d_out;

    float *kc, *vt, *qc, *qr, *kr2;
    cudaGetSymbolAddress((void**)&kc,  g_kc);
    cudaGetSymbolAddress((void**)&vt,  g_vt);
    cudaGetSymbolAddress((void**)&qc,  g_qc);
    cudaGetSymbolAddress((void**)&qr,  g_qr);
    cudaGetSymbolAddress((void**)&kr2, g_kr2);

    __nv_bfloat16 *xh, *xl, *ckvh, *ckvl, *cqh, *cql, *aoh, *aol;
    __nv_bfloat16 *wdkvh, *wdkvl, *wdqkrh, *wdqkrl, *wukvh, *wukvl, *wuqrh, *wuqrl, *woh, *wol;
    cudaGetSymbolAddress((void**)&xh, g_xh);     cudaGetSymbolAddress((void**)&xl, g_xl);
    cudaGetSymbolAddress((void**)&ckvh, g_ckvh); cudaGetSymbolAddress((void**)&ckvl, g_ckvl);
    cudaGetSymbolAddress((void**)&cqh, g_cqh);   cudaGetSymbolAddress((void**)&cql, g_cql);
    cudaGetSymbolAddress((void**)&aoh, g_aoh);   cudaGetSymbolAddress((void**)&aol, g_aol);
    cudaGetSymbolAddress((void**)&wdkvh, g_wdkvh);   cudaGetSymbolAddress((void**)&wdkvl, g_wdkvl);
    cudaGetSymbolAddress((void**)&wdqkrh, g_wdqkrh); cudaGetSymbolAddress((void**)&wdqkrl, g_wdqkrl);
    cudaGetSymbolAddress((void**)&wukvh, g_wukvh);   cudaGetSymbolAddress((void**)&wukvl, g_wukvl);
    cudaGetSymbolAddress((void**)&wuqrh, g_wuqrh);   cudaGetSymbolAddress((void**)&wuqrl, g_wuqrl);
    cudaGetSymbolAddress((void**)&woh, g_woh);       cudaGetSymbolAddress((void**)&wol, g_wol);

    cudaFuncSetAttribute(mm_mma_kernel, cudaFuncAttributeMaxDynamicSharedMemorySize, MM_SMEM);
    cudaFuncSetAttribute(flashmma_kernel, cudaFuncAttributeMaxDynamicSharedMemorySize, FLASH_SMEM);

    dim3 tsb(32, 8);
    // stacked transposed weight splits
    tsplit_kernel<<<dim3(DCs/32, Dsz/32), tsb>>>(W_DKV, wdkvh, wdkvl, Dsz, DCs);
    tsplit_kernel<<<dim3(DCs/32, Dsz/32), tsb>>>(W_DQ,  wdqkrh, wdqkrl, Dsz, DCs);
    tsplit_kernel<<<dim3(DHRs/32, Dsz/32), tsb>>>(W_KR, wdqkrh + (size_t)DCs*Dsz, wdqkrl + (size_t)DCs*Dsz, Dsz, DHRs);
    tsplit_kernel<<<dim3(Dsz/32, DCs/32), tsb>>>(W_UK,  wukvh, wukvl, DCs, Dsz);
    tsplit_kernel<<<dim3(Dsz/32, DCs/32), tsb>>>(W_UV,  wukvh + (size_t)Dsz*DCs, wukvl + (size_t)Dsz*DCs, DCs, Dsz);
    tsplit_kernel<<<dim3(Dsz/32, DCs/32), tsb>>>(W_UQ,  wuqrh, wuqrl, DCs, Dsz);
    tsplit_kernel<<<dim3((NHs*DHRs)/32, DCs/32), tsb>>>(W_QR, wuqrh + (size_t)Dsz*DCs, wuqrl + (size_t)Dsz*DCs, DCs, NHs*DHRs);
    tsplit_kernel<<<dim3(Dsz/32, Dsz/32), tsb>>>(W_O,   woh,   wol,   Dsz, Dsz);

    { int n = Msz * Dsz; split_kernel<<<(n / 4 + 255) / 256, 256>>>(x, xh, xl, n); }

    // down-projections: DKV -> bf16; DQ+KR combined -> bf16 + fp32 kr2
    mm_mma_kernel<<<dim3(DCs/128, Msz/128), 256, MM_SMEM>>>(
        xh, xl, wdkvh, wdkvl, nullptr, ckvh, ckvl, nullptr, Msz, DCs, Dsz, DCs);
    mm_mma_kernel<<<dim3((DCs+128)/128, Msz/128), 256, MM_SMEM>>>(
        xh, xl, wdqkrh, wdqkrl, nullptr, cqh, cql, kr2, Msz, DCs+128, Dsz, DCs);

    // up-projections: UK+UV combined; UQ+QR combined
    mm_mma_kernel<<<dim3((2*Dsz)/128, Msz/128), 256, MM_SMEM>>>(
        ckvh, ckvl, wukvh, wukvl, kc, nullptr, nullptr, vt, Msz, 2*Dsz, DCs, Dsz);
    mm_mma_kernel<<<dim3((Dsz+NHs*DHRs)/128, Msz/128), 256, MM_SMEM>>>(
        cqh, cql, wuqrh, wuqrl, qc, nullptr, nullptr, qr, Msz, Dsz+NHs*DHRs, DCs, Dsz);

    // RoPE + concat + normalize -> bf16 hi/lo Q,K,V
    assemble_kernel<<<Msz, 512>>>(s_qk);

    // tensor-core causal flash attention -> aoh/aol
    flashmma_kernel<<<dim3(Lsz / FQ, NHs, Bsz), 256, FLASH_SMEM>>>();

    // output projection
    mm_mma_kernel<<<dim3(Dsz/128, Msz/128), 256, MM_SMEM>>>(
        aoh, aol, woh, wol, out, nullptr, nullptr, nullptr, Msz, Dsz, Dsz, Dsz);
}

// round 9
// speedup vs baseline: 4.7912x; 1.1168x over previous
#include <cuda_runtime.h>
#include <cuda_bf16.h>
#include <math.h>
#include <stdint.h>

// ---------------- problem constants ----------------
#define Bsz   4
#define Lsz   2048
#define Dsz   2048
#define NHs   16
#define DHs   128
#define DHRs  64
#define DCs   1024
#define DTOT  (DHs + DHRs)     // 192
#define Msz   (Bsz * Lsz)      // 8192

// ---------------- fp32 scratch ----------------
__device__ float g_kc [Msz * Dsz];
__device__ float g_vt [Msz * Dsz];
__device__ float g_qc [Msz * Dsz];
__device__ float g_qr [Msz * (NHs * DHRs)];
__device__ float g_kr2[Msz * 128];            // padded KR output (cols 64..127 unused)

// ---------------- bf16 split scratch ----------------
__device__ __align__(256) __nv_bfloat16 g_xh [Msz * Dsz];
__device__ __align__(256) __nv_bfloat16 g_xl [Msz * Dsz];
// combined c_kv | c_q  [Msz x 2048]: cols 0..1023 = c_kv, 1024..2047 = c_q
__device__ __align__(256) __nv_bfloat16 g_ckvqh[Msz * 2048];
__device__ __align__(256) __nv_bfloat16 g_ckvql[Msz * 2048];
__device__ __align__(256) __nv_bfloat16 g_aoh [Msz * Dsz];
__device__ __align__(256) __nv_bfloat16 g_aol [Msz * Dsz];
// attention operands, hi/lo
__device__ __align__(256) __nv_bfloat16 g_Qh [Bsz*NHs*Lsz*DTOT], g_Ql [Bsz*NHs*Lsz*DTOT];
__device__ __align__(256) __nv_bfloat16 g_Kh [Bsz*NHs*Lsz*DTOT], g_Kl [Bsz*NHs*Lsz*DTOT];
__device__ __align__(256) __nv_bfloat16 g_Vh [Bsz*NHs*Lsz*DHs],  g_Vl [Bsz*NHs*Lsz*DHs];
// stacked transposed weights [N x K] hi/lo
// wd: [DKV(1024) | DQ(1024) | KR(128, rows 64..127 zero)] x 2048  => 2176 rows
__device__ __align__(256) __nv_bfloat16 g_wdh[2176 * 2048], g_wdl[2176 * 2048];
// wu: [UK(2048) | UV(2048) | UQ(2048) | QR(1024)] x 1024 => 7168 rows
__device__ __align__(256) __nv_bfloat16 g_wuh[7168 * 1024], g_wul[7168 * 1024];
__device__ __align__(256) __nv_bfloat16 g_woh[Dsz * Dsz],   g_wol[Dsz * Dsz];

// ---------------- PTX helpers (baseline ISA only) ----------------
__device__ __forceinline__ uint32_t smem_u32(const void* p) {
    uint32_t a;
    asm("{ .reg .u64 t; cvta.to.shared.u64 t, %1; cvt.u32.u64 %0, t; }" : "=r"(a) : "l"(p));
    return a;
}
__device__ __forceinline__ void cpa16(uint32_t s, const void* g) {
    asm volatile("cp.async.cg.shared.global [%0], [%1], 16;" :: "r"(s), "l"(g) : "memory");
}
__device__ __forceinline__ void cp_commit() {
    asm volatile("cp.async.commit_group;" ::: "memory");
}
template <int N> __device__ __forceinline__ void cp_wait_group() {
    asm volatile("cp.async.wait_group %0;" :: "n"(N) : "memory");
}
__device__ __forceinline__ void ldm_x4(uint32_t* r, uint32_t addr) {
    asm volatile("ldmatrix.sync.aligned.m8n8.x4.shared.b16 {%0,%1,%2,%3}, [%4];"
                 : "=r"(r[0]), "=r"(r[1]), "=r"(r[2]), "=r"(r[3]) : "r"(addr));
}
__device__ __forceinline__ void ldm_x4_t(uint32_t* r, uint32_t addr) {
    asm volatile("ldmatrix.sync.aligned.m8n8.x4.trans.shared.b16 {%0,%1,%2,%3}, [%4];"
                 : "=r"(r[0]), "=r"(r[1]), "=r"(r[2]), "=r"(r[3]) : "r"(addr));
}
__device__ __forceinline__ void mma_bf16(float* c, const uint32_t* a, const uint32_t* b) {
    asm volatile(
        "mma.sync.aligned.m16n8k16.row.col.f32.bf16.bf16.f32 "
        "{%0,%1,%2,%3}, {%4,%5,%6,%7}, {%8,%9}, {%0,%1,%2,%3};"
        : "+f"(c[0]), "+f"(c[1]), "+f"(c[2]), "+f"(c[3])
        : "r"(a[0]), "r"(a[1]), "r"(a[2]), "r"(a[3]), "r"(b[0]), "r"(b[1]));
}
__device__ __forceinline__ uint32_t pack_bf162(float a, float b) {
    __nv_bfloat162 t;
    t.x = __float2bfloat16(a); t.y = __float2bfloat16(b);
    return *(uint32_t*)&t;
}

// ---------------- split / transpose-split conversions ----------------
__global__ void split_kernel(const float* __restrict__ src,
                             __nv_bfloat16* __restrict__ hi,
                             __nv_bfloat16* __restrict__ lo, int n) {
    int i = (blockIdx.x * 256 + threadIdx.x) * 4;
    if (i < n) {
        float4 v = *(const float4*)&src[i];
        __nv_bfloat162 h0, h1, l0, l1;
        h0.x = __float2bfloat16(v.x); h0.y = __float2bfloat16(v.y);
        h1.x = __float2bfloat16(v.z); h1.y = __float2bfloat16(v.w);
        l0.x = __float2bfloat16(v.x - __bfloat162float(h0.x));
        l0.y = __float2bfloat16(v.y - __bfloat162float(h0.y));
        l1.x = __float2bfloat16(v.z - __bfloat162float(h1.x));
        l1.y = __float2bfloat16(v.w - __bfloat162float(h1.y));
        *(__nv_bfloat162*)&hi[i]     = h0;
        *(__nv_bfloat162*)&hi[i + 2] = h1;
        *(__nv_bfloat162*)&lo[i]     = l0;
        *(__nv_bfloat162*)&lo[i + 2] = l1;
    }
}

// W[K x N] row-major -> Th/Tl [N x K] row-major bf16 hi/lo
__global__ void tsplit_kernel(const float* __restrict__ W,
                              __nv_bfloat16* __restrict__ Th,
                              __nv_bfloat16* __restrict__ Tl, int K, int N) {
    __shared__ float t[32][33];
    int kb = blockIdx.y * 32, nb = blockIdx.x * 32;
    int tx = threadIdx.x, ty = threadIdx.y;    // (32, 8)
#pragma unroll
    for (int r = 0; r < 32; r += 8)
        t[ty + r][tx] = W[(size_t)(kb + ty + r) * N + nb + tx];
    __syncthreads();
#pragma unroll
    for (int r = 0; r < 32; r += 8) {
        float x = t[tx][ty + r];
        __nv_bfloat16 h = __float2bfloat16(x);
        float res = x - __bfloat162float(h);
        size_t o = (size_t)(nb + ty + r) * K + kb + tx;
        Th[o] = h;
        Tl[o] = __float2bfloat16(res);
    }
}

// ---------------- mma.sync bf16 split-3 GEMM v2 ----------------
// CTA tile 256x128x32, 8 warps (4m x 2n), warp tile 64x64, 3-stage cp.async.
// Output regions of 2048 cols: region r -> fp32 f[r] (stride min(2048, Nd-r*2048));
// region 0 with f0==null -> bf16 hi/lo pair Ch/Cl (stride 2048).
#define MMS_A_H 0
#define MMS_A_L 16384
#define MMS_B_H 32768
#define MMS_B_L 40960
#define MMS_STAGE 49152
#define MM_SMEM (3 * MMS_STAGE)   // 147456

__device__ __forceinline__ void mm_load_stage(
    uint32_t sbase,
    const __nv_bfloat16* __restrict__ Ah, const __nv_bfloat16* __restrict__ Al, int Astride,
    const __nv_bfloat16* __restrict__ Bh, const __nv_bfloat16* __restrict__ Bl,
    int m0, int n0, int k0, int Kd, int tid)
{
#pragma unroll
    for (int t = 0; t < 4; ++t) {
        int idx = tid + t * 256;            // 0..1023 : A 256 rows x 4 chunks
        int row = idx >> 2, c = idx & 3;
        uint32_t so = (uint32_t)(row * 64 + ((c ^ (row & 3)) << 4));
        size_t g = (size_t)(m0 + row) * Astride + k0 + c * 8;
        cpa16(sbase + MMS_A_H + so, Ah + g);
        cpa16(sbase + MMS_A_L + so, Al + g);
    }
#pragma unroll
    for (int t = 0; t < 2; ++t) {
        int idx = tid + t * 256;            // 0..511 : B 128 rows x 4 chunks
        int row = idx >> 2, c = idx & 3;
        uint32_t so = (uint32_t)(row * 64 + ((c ^ (row & 3)) << 4));
        size_t g = (size_t)(n0 + row) * Kd + k0 + c * 8;
        cpa16(sbase + MMS_B_H + so, Bh + g);
        cpa16(sbase + MMS_B_L + so, Bl + g);
    }
}

__global__ void __launch_bounds__(256, 1)
mm_mma_kernel(const __nv_bfloat16* __restrict__ Ahg, const __nv_bfloat16* __restrict__ Alg,
              const __nv_bfloat16* __restrict__ Ahg2, const __nv_bfloat16* __restrict__ Alg2,
              int aswitch, int Astride,
              const __nv_bfloat16* __restrict__ Bhg, const __nv_bfloat16* __restrict__ Blg,
              float* __restrict__ f0, float* __restrict__ f1,
              float* __restrict__ f2, float* __restrict__ f3,
              __nv_bfloat16* __restrict__ Ch, __nv_bfloat16* __restrict__ Cl,
              int Nd, int Kd) {
    extern __shared__ __align__(1024) char smem[];
    const uint32_t sb = smem_u32(smem);
    const int tid = threadIdx.x, wid = tid >> 5, lane = tid & 31;
    const int m0 = blockIdx.y * 256, n0 = blockIdx.x * 128;
    const int mw = (wid & 3) * 64;
    const int nw = (wid >> 2) * 64;

    const __nv_bfloat16* Auh = (n0 >= aswitch) ? Ahg2 : Ahg;
    const __nv_bfloat16* Aul = (n0 >= aswitch) ? Alg2 : Alg;

    float acc[4][8][4];
#pragma unroll
    for (int i = 0; i < 4; ++i)
#pragma unroll
        for (int j = 0; j < 8; ++j)
#pragma unroll
            for (int q = 0; q < 4; ++q) acc[i][j][q] = 0.f;

    const int nk = Kd >> 5;
    mm_load_stage(sb + 0 * MMS_STAGE, Auh, Aul, Astride, Bhg, Blg, m0, n0, 0, Kd, tid);
    cp_commit();
    mm_load_stage(sb + 1 * MMS_STAGE, Auh, Aul, Astride, Bhg, Blg, m0, n0, 32, Kd, tid);
    cp_commit();

    const int jA = lane >> 3, rA = lane & 7;

    int sidx = 0;
    for (int it = 0; it < nk; ++it) {
        cp_wait_group<1>();
        __syncthreads();

        if (it + 2 < nk) {
            int ps = sidx + 2; if (ps >= 3) ps -= 3;
            mm_load_stage(sb + ps * MMS_STAGE, Auh, Aul, Astride, Bhg, Blg,
                          m0, n0, (it + 2) << 5, Kd, tid);
        }
        cp_commit();

        const uint32_t stg = sb + sidx * MMS_STAGE;

#pragma unroll
        for (int ks = 0; ks < 2; ++ks) {
            uint32_t ah[4][4], al[4][4];
#pragma unroll
            for (int i = 0; i < 4; ++i) {
                int m = mw + i * 16 + ((jA & 1) << 3) + rA;
                int c = (ks << 1) + (jA >> 1);
                uint32_t off = (uint32_t)(m * 64 + ((c ^ (m & 3)) << 4));
                ldm_x4(ah[i], stg + MMS_A_H + off);
                ldm_x4(al[i], stg + MMS_A_L + off);
            }
            uint32_t bh[8][2], bl[8][2];
#pragma unroll
            for (int p = 0; p < 4; ++p) {
                int n = nw + p * 16 + ((jA >> 1) << 3) + rA;
                int c = (ks << 1) + (jA & 1);
                uint32_t off = (uint32_t)(n * 64 + ((c ^ (n & 3)) << 4));
                uint32_t tmp[4];
                ldm_x4(tmp, stg + MMS_B_H + off);
                bh[2 * p][0] = tmp[0]; bh[2 * p][1] = tmp[1];
                bh[2 * p + 1][0] = tmp[2]; bh[2 * p + 1][1] = tmp[3];
                ldm_x4(tmp, stg + MMS_B_L + off);
                bl[2 * p][0] = tmp[0]; bl[2 * p][1] = tmp[1];
                bl[2 * p + 1][0] = tmp[2]; bl[2 * p + 1][1] = tmp[3];
            }
#pragma unroll
            for (int i = 0; i < 4; ++i)
#pragma unroll
                for (int j = 0; j < 8; ++j) {
                    mma_bf16(acc[i][j], ah[i], bh[j]);
                    mma_bf16(acc[i][j], al[i], bh[j]);
                    mma_bf16(acc[i][j], ah[i], bl[j]);
                }
        }
        if (++sidx == 3) sidx = 0;
    }

    // ---- region epilogue ----
#pragma unroll
    for (int i = 0; i < 4; ++i) {
        int row = m0 + mw + i * 16 + (lane >> 2);
#pragma unroll
        for (int j = 0; j < 8; ++j) {
            int col = n0 + nw + j * 8 + ((lane & 3) << 1);
            int r = col >> 11;
            int base = r << 11;
            int stride = Nd - base; if (stride > 2048) stride = 2048;
            int cc = col - base;
            float* fr = (r == 0) ? f0 : (r == 1) ? f1 : (r == 2) ? f2 : f3;
            if (fr) {
                *(float2*)&fr[(size_t)row * stride + cc]       = make_float2(acc[i][j][0], acc[i][j][1]);
                *(float2*)&fr[(size_t)(row + 8) * stride + cc] = make_float2(acc[i][j][2], acc[i][j][3]);
            } else {
#pragma unroll
                for (int hh = 0; hh < 2; ++hh) {
                    float v0 = acc[i][j][2 * hh], v1 = acc[i][j][2 * hh + 1];
                    __nv_bfloat162 h2, l2;
                    h2.x = __float2bfloat16(v0); h2.y = __float2bfloat16(v1);
                    l2.x = __float2bfloat16(v0 - __bfloat162float(h2.x));
                    l2.y = __float2bfloat16(v1 - __bfloat162float(h2.y));
                    size_t o = (size_t)(row + 8 * hh) * stride + cc;
                    *(__nv_bfloat162*)&Ch[o] = h2;
                    *(__nv_bfloat162*)&Cl[o] = l2;
                }
            }
        }
    }
}

// ---------------- assemble: RoPE + concat + normalize -> bf16 hi/lo Q,K,V ----------------
#define LOG2_ROPE_BASE 13.287712379549449f

__global__ void __launch_bounds__(512)
assemble_kernel(const float* __restrict__ s_qk_ptr) {
    const int bl = blockIdx.x;
    const int b  = bl / Lsz;
    const int l  = bl % Lsz;
    const int w    = threadIdx.x >> 5;
    const int lane = threadIdx.x & 31;
    const float s_qk = *s_qk_ptr;

    float qv[3][2], kv[3][2];
    float ssq = 0.f, ssk = 0.f;

#pragma unroll
    for (int j = 0; j < 3; ++j) {
        if (j < 2) {
            int d = j * 64 + lane * 2;
            float2 qq = *(const float2*)&g_qc[(size_t)bl * Dsz + w * DHs + d];
            float2 kk = *(const float2*)&g_kc[(size_t)bl * Dsz + w * DHs + d];
            qv[j][0] = qq.x; qv[j][1] = qq.y;
            kv[j][0] = kk.x; kv[j][1] = kk.y;
        } else {
            int dr = lane * 2;
            const float* qrp = &g_qr[(size_t)bl * (NHs * DHRs) + w * DHRs];
            const float* krp = &g_kr2[(size_t)bl * 128];
            float2 q1 = *(const float2*)&qrp[dr];
            float2 k1 = *(const float2*)&krp[dr];
            float2 q2, k2;
            float sgn;
            if (dr < 32) {
                q2 = *(const float2*)&qrp[dr + 32];
                k2 = *(const float2*)&krp[dr + 32];
                sgn = -1.f;
            } else {
                q2 = *(const float2*)&qrp[dr - 32];
                k2 = *(const float2*)&krp[dr - 32];
                sgn = 1.f;
            }
#pragma unroll
            for (int e = 0; e < 2; ++e) {
                int i = (dr + e) & 31;
                float invf = exp2f(-(float)i * (LOG2_ROPE_BASE / 32.0f));
                float ang  = (float)l * invf;
                float sn, cs;
                sincosf(ang, &sn, &cs);
                float x1 = e ? q1.y : q1.x;
                float x2 = sgn * (e ? q2.y : q2.x);
                float y1 = e ? k1.y : k1.x;
                float y2 = sgn * (e ? k2.y : k2.x);
                qv[2][e] = x1 * cs + x2 * sn;
                kv[2][e] = y1 * cs + y2 * sn;
            }
        }
        ssq += qv[j][0] * qv[j][0] + qv[j][1] * qv[j][1];
        ssk += kv[j][0] * kv[j][0] + kv[j][1] * kv[j][1];
    }
#pragma unroll
    for (int o = 16; o; o >>= 1) {
        ssq += __shfl_xor_sync(0xffffffffu, ssq, o);
        ssk += __shfl_xor_sync(0xffffffffu, ssk, o);
    }
    float qn = s_qk / fmaxf(sqrtf(ssq), 1e-12f);
    float kn = 1.0f / fmaxf(sqrtf(ssk), 1e-12f);

    size_t base = ((size_t)(b * NHs + w) * Lsz + l);
#pragma unroll
    for (int j = 0; j < 3; ++j) {
        int d = j * 64 + lane * 2;
        float q0 = qv[j][0] * qn, q1 = qv[j][1] * qn;
        float k0 = kv[j][0] * kn, k1 = kv[j][1] * kn;
        __nv_bfloat162 h2, l2;
        h2.x = __float2bfloat16(q0); h2.y = __float2bfloat16(q1);
        l2.x = __float2bfloat16(q0 - __bfloat162float(h2.x));
        l2.y = __float2bfloat16(q1 - __bfloat162float(h2.y));
        *(__nv_bfloat162*)&g_Qh[base * DTOT + d] = h2;
        *(__nv_bfloat162*)&g_Ql[base * DTOT + d] = l2;
        h2.x = __float2bfloat16(k0); h2.y = __float2bfloat16(k1);
        l2.x = __float2bfloat16(k0 - __bfloat162float(h2.x));
        l2.y = __float2bfloat16(k1 - __bfloat162float(h2.y));
        *(__nv_bfloat162*)&g_Kh[base * DTOT + d] = h2;
        *(__nv_bfloat162*)&g_Kl[base * DTOT + d] = l2;
    }
#pragma unroll
    for (int dd = 0; dd < 2; ++dd) {
        int d = dd * 64 + lane * 2;
        float2 vv = *(const float2*)&g_vt[(size_t)bl * Dsz + w * DHs + d];
        __nv_bfloat162 h2, l2;
        h2.x = __float2bfloat16(vv.x); h2.y = __float2bfloat16(vv.y);
        l2.x = __float2bfloat16(vv.x - __bfloat162float(h2.x));
        l2.y = __float2bfloat16(vv.y - __bfloat162float(h2.y));
        *(__nv_bfloat162*)&g_Vh[base * DHs + d] = h2;
        *(__nv_bfloat162*)&g_Vl[base * DHs + d] = l2;
    }
}

// ---------------- tensor-core causal flash attention (split-3 bf16, register P) ----------------
#define FQ 128
#define FK 64
#define SQH 0
#define SQL (SQH + FQ*384)           // 49152
#define SKH (SQL + FQ*384)           // 98304
#define SKL (SKH + FK*384)           // 122880
#define SV0H (SKL + FK*384)          // 147456
#define SV0L (SV0H + FK*256)         // 163840
#define SV1H (SV0L + FK*256)         // 180224
#define SV1L (SV1H + FK*256)         // 196608
#define FLASH_SMEM (SV1L + FK*256)   // 212992

__device__ __forceinline__ void fl_load_qk(
    uint32_t sb, uint32_t offH, uint32_t offL, int rows,
    const __nv_bfloat16* __restrict__ Gh, const __nv_bfloat16* __restrict__ Gl,
    size_t gbase, int tid)
{
    for (int idx = tid; idx < rows * 24; idx += 256) {
        int r = idx / 24, c = idx % 24;
        uint32_t so = (uint32_t)(r * 384 + ((c ^ (r & 7)) << 4));
        size_t g = gbase + (size_t)r * DTOT + c * 8;
        cpa16(sb + offH + so, Gh + g);
        cpa16(sb + offL + so, Gl + g);
    }
}
__device__ __forceinline__ void fl_load_v(
    uint32_t sb, uint32_t vH, uint32_t vL,
    const __nv_bfloat16* __restrict__ Gh, const __nv_bfloat16* __restrict__ Gl,
    size_t gbase, int tid)
{
    for (int idx = tid; idx < FK * 16; idx += 256) {
        int r = idx >> 4, c = idx & 15;
        uint32_t so = (uint32_t)(r * 256 + ((c ^ (r & 7)) << 4));
        size_t g = gbase + (size_t)r * DHs + c * 8;
        cpa16(sb + vH + so, Gh + g);
        cpa16(sb + vL + so, Gl + g);
    }
}

__global__ void __launch_bounds__(256, 1)
flashmma_kernel() {
    extern __shared__ __align__(1024) char sm[];
    const uint32_t sb = smem_u32(sm);
    const int tid = threadIdx.x, w = tid >> 5, lane = tid & 31;
    const int qt = (int)(gridDim.x - 1u - blockIdx.x);
    const int h = blockIdx.y, b = blockIdx.z;
    const int q0 = qt * FQ;
    const int mw = w * 16;
    const int jA = lane >> 3, rA = lane & 7;

    const size_t qkb = (size_t)(b * NHs + h) * Lsz;
    fl_load_qk(sb, SQH, SQL, FQ, g_Qh, g_Ql, (qkb + q0) * DTOT, tid);
    cp_commit();                                    // group: Q
    fl_load_qk(sb, SKH, SKL, FK, g_Kh, g_Kl, qkb * DTOT, tid);
    fl_load_v(sb, SV0H, SV0L, g_Vh, g_Vl, qkb * DHs, tid);
    cp_commit();                                    // group: G0 = {K0, V0}

    float oacc[16][4];
#pragma unroll
    for (int j = 0; j < 16; ++j)
#pragma unroll
        for (int q = 0; q < 4; ++q) oacc[j][q] = 0.f;
    float m0 = -1e30f, m1 = -1e30f, l0 = 0.f, l1 = 0.f;

    const int nkt = 2 * qt + 2;
    const int r0loc = mw + (lane >> 2);
    const int gr0 = q0 + r0loc;

    for (int kt = 0; kt < nkt; ++kt) {
        cp_wait_group<0>();      // K(kt), V(kt) (and Q on first iter) complete
        __syncthreads();

        // ---- S = Q K^T (split-3) ----
        float sacc[8][4];
#pragma unroll
        for (int j = 0; j < 8; ++j)
#pragma unroll
            for (int q = 0; q < 4; ++q) sacc[j][q] = 0.f;

#pragma unroll
        for (int ks = 0; ks < 12; ++ks) {
            int arow = mw + ((jA & 1) << 3) + rA;
            int achk = ks * 2 + (jA >> 1);
            uint32_t aoff = (uint32_t)(arow * 384 + ((achk ^ (arow & 7)) << 4));
            uint32_t ah[4], al[4];
            ldm_x4(ah, sb + SQH + aoff);
            ldm_x4(al, sb + SQL + aoff);
            uint32_t bh[8][2], bl[8][2];
#pragma unroll
            for (int p = 0; p < 4; ++p) {
                int brow = p * 16 + ((jA >> 1) << 3) + rA;
                int bchk = ks * 2 + (jA & 1);
                uint32_t boff = (uint32_t)(brow * 384 + ((bchk ^ (brow & 7)) << 4));
                uint32_t tmp[4];
                ldm_x4(tmp, sb + SKH + boff);
                bh[2 * p][0] = tmp[0]; bh[2 * p][1] = tmp[1];
                bh[2 * p + 1][0] = tmp[2]; bh[2 * p + 1][1] = tmp[3];
                ldm_x4(tmp, sb + SKL + boff);
                bl[2 * p][0] = tmp[0]; bl[2 * p][1] = tmp[1];
                bl[2 * p + 1][0] = tmp[2]; bl[2 * p + 1][1] = tmp[3];
            }
#pragma unroll
            for (int j = 0; j < 8; ++j) {
                mma_bf16(sacc[j], ah, bh[j]);
                mma_bf16(sacc[j], al, bh[j]);
                mma_bf16(sacc[j], ah, bl[j]);
            }
        }

        // ---- causal mask (last two k-tiles only) ----
        if (kt >= 2 * qt) {
            int k0 = kt * FK;
#pragma unroll
            for (int j = 0; j < 8; ++j) {
                int col = k0 + j * 8 + ((lane & 3) << 1);
                if (col > gr0)     sacc[j][0] = -1e30f;
                if (col + 1 > gr0) sacc[j][1] = -1e30f;
                if (col > gr0 + 8)     sacc[j][2] = -1e30f;
                if (col + 1 > gr0 + 8) sacc[j][3] = -1e30f;
            }
        }

        // ---- online softmax (register P, hi/lo fragments) ----
        float mx0 = -1e30f, mx1 = -1e30f;
#pragma unroll
        for (int j = 0; j < 8; ++j) {
            mx0 = fmaxf(mx0, fmaxf(sacc[j][0], sacc[j][1]));
            mx1 = fmaxf(mx1, fmaxf(sacc[j][2], sacc[j][3]));
        }
#pragma unroll
        for (int o = 1; o <= 2; o <<= 1) {
            mx0 = fmaxf(mx0, __shfl_xor_sync(0xffffffffu, mx0, o));
            mx1 = fmaxf(mx1, __shfl_xor_sync(0xffffffffu, mx1, o));
        }
        float mn0 = fmaxf(m0, mx0), mn1 = fmaxf(m1, mx1);
        float sc0 = __expf(m0 - mn0), sc1 = __expf(m1 - mn1);
        m0 = mn0; m1 = mn1;

        uint32_t pfh[4][4], pfl[4][4];
        float rs0 = 0.f, rs1 = 0.f;
#pragma unroll
        for (int j = 0; j < 8; ++j) {
            float p0 = __expf(sacc[j][0] - mn0);
            float p1 = __expf(sacc[j][1] - mn0);
            float p2 = __expf(sacc[j][2] - mn1);
            float p3 = __expf(sacc[j][3] - mn1);
            rs0 += p0 + p1; rs1 += p2 + p3;
            __nv_bfloat162 h01, h23;
            h01.x = __float2bfloat16(p0); h01.y = __float2bfloat16(p1);
            h23.x = __float2bfloat16(p2); h23.y = __float2bfloat16(p3);
            int t = j >> 1, s = (j & 1) * 2;
            pfh[t][s + 0] = *(uint32_t*)&h01;
            pfh[t][s + 1] = *(uint32_t*)&h23;
            pfl[t][s + 0] = pack_bf162(p0 - __bfloat162float(h01.x),
                                       p1 - __bfloat162float(h01.y));
            pfl[t][s + 1] = pack_bf162(p2 - __bfloat162float(h23.x),
                                       p3 - __bfloat162float(h23.y));
        }
#pragma unroll
        for (int o = 1; o <= 2; o <<= 1) {
            rs0 += __shfl_xor_sync(0xffffffffu, rs0, o);
            rs1 += __shfl_xor_sync(0xffffffffu, rs1, o);
        }
        l0 = l0 * sc0 + rs0;
        l1 = l1 * sc1 + rs1;
#pragma unroll
        for (int j = 0; j < 16; ++j) {
            oacc[j][0] *= sc0; oacc[j][1] *= sc0;
            oacc[j][2] *= sc1; oacc[j][3] *= sc1;
        }

        __syncthreads();                // all warps done reading K(kt) / V buffers safe

        if (kt + 1 < nkt) {
            fl_load_qk(sb, SKH, SKL, FK, g_Kh, g_Kl, (qkb + (size_t)(kt + 1) * FK) * DTOT, tid);
            uint32_t vH = ((kt + 1) & 1) ? SV1H : SV0H;
            uint32_t vL = ((kt + 1) & 1) ? SV1L : SV0L;
            fl_load_v(sb, vH, vL, g_Vh, g_Vl, (qkb + (size_t)(kt + 1) * FK) * DHs, tid);
        }
        cp_commit();                    // group G(kt+1)

        // ---- O += P V (split-3), V from buffer kt&1, P from registers ----
        const uint32_t vH = (kt & 1) ? SV1H : SV0H;
        const uint32_t vL = (kt & 1) ? SV1L : SV0L;
#pragma unroll
        for (int ks = 0; ks < 4; ++ks) {
            int key = ks * 16 + (lane & 15);
#pragma unroll
            for (int p = 0; p < 8; ++p) {
                int dch = p * 2 + (lane >> 4);
                uint32_t voff = (uint32_t)(key * 256 + ((dch ^ (key & 7)) << 4));
                uint32_t th[4], tl[4];
                ldm_x4_t(th, sb + vH + voff);
                ldm_x4_t(tl, sb + vL + voff);
                mma_bf16(oacc[2 * p], pfh[ks], th);
                mma_bf16(oacc[2 * p], pfl[ks], th);
                mma_bf16(oacc[2 * p], pfh[ks], tl);
                mma_bf16(oacc[2 * p + 1], pfh[ks], th + 2);
                mma_bf16(oacc[2 * p + 1], pfl[ks], th + 2);
                mma_bf16(oacc[2 * p + 1], pfh[ks], tl + 2);
            }
        }
    }

    // ---- epilogue: normalize, split, write (B,L,D) bf16 hi/lo ----
    float inv0 = 1.0f / l0, inv1 = 1.0f / l1;
    size_t ob0 = ((size_t)(b * Lsz + gr0)) * Dsz + h * DHs;
    size_t ob1 = ((size_t)(b * Lsz + gr0 + 8)) * Dsz + h * DHs;
#pragma unroll
    for (int j = 0; j < 16; ++j) {
        int d = j * 8 + ((lane & 3) << 1);
        float v0 = oacc[j][0] * inv0, v1 = oacc[j][1] * inv0;
        __nv_bfloat162 h2, l2;
        h2.x = __float2bfloat16(v0); h2.y = __float2bfloat16(v1);
        l2.x = __float2bfloat16(v0 - __bfloat162float(h2.x));
        l2.y = __float2bfloat16(v1 - __bfloat162float(h2.y));
        *(__nv_bfloat162*)&g_aoh[ob0 + d] = h2;
        *(__nv_bfloat162*)&g_aol[ob0 + d] = l2;
        float v2 = oacc[j][2] * inv1, v3 = oacc[j][3] * inv1;
        h2.x = __float2bfloat16(v2); h2.y = __float2bfloat16(v3);
        l2.x = __float2bfloat16(v2 - __bfloat162float(h2.x));
        l2.y = __float2bfloat16(v3 - __bfloat162float(h2.y));
        *(__nv_bfloat162*)&g_aoh[ob1 + d] = h2;
        *(__nv_bfloat162*)&g_aol[ob1 + d] = l2;
    }
}

// ---------------- launcher ----------------
extern "C" void kernel_launch(void* const* d_in, const int* in_sizes, int n_in,
                              void* d_out, int out_size) {
    const float* x     = (const float*)d_in[0];
    const float* W_DKV = (const float*)d_in[1];
    const float* W_UK  = (const float*)d_in[2];
    const float* W_UV  = (const float*)d_in[3];
    const float* W_DQ  = (const float*)d_in[4];
    const float* W_UQ  = (const float*)d_in[5];
    const float* W_QR  = (const float*)d_in[6];
    const float* W_KR  = (const float*)d_in[7];
    const float* W_O   = (const float*)d_in[8];
    const float* s_qk  = (const float*)d_in[9];
    float* out = (float*)d_out;

    float *kc, *vt, *qc, *qr, *kr2;
    cudaGetSymbolAddress((void**)&kc,  g_kc);
    cudaGetSymbolAddress((void**)&vt,  g_vt);
    cudaGetSymbolAddress((void**)&qc,  g_qc);
    cudaGetSymbolAddress((void**)&qr,  g_qr);
    cudaGetSymbolAddress((void**)&kr2, g_kr2);

    __nv_bfloat16 *xh, *xl, *cvh, *cvl, *aoh, *aol;
    __nv_bfloat16 *wdh, *wdl, *wuh, *wul, *woh, *wol;
    cudaGetSymbolAddress((void**)&xh, g_xh);     cudaGetSymbolAddress((void**)&xl, g_xl);
    cudaGetSymbolAddress((void**)&cvh, g_ckvqh); cudaGetSymbolAddress((void**)&cvl, g_ckvql);
    cudaGetSymbolAddress((void**)&aoh, g_aoh);   cudaGetSymbolAddress((void**)&aol, g_aol);
    cudaGetSymbolAddress((void**)&wdh, g_wdh);   cudaGetSymbolAddress((void**)&wdl, g_wdl);
    cudaGetSymbolAddress((void**)&wuh, g_wuh);   cudaGetSymbolAddress((void**)&wul, g_wul);
    cudaGetSymbolAddress((void**)&woh, g_woh);   cudaGetSymbolAddress((void**)&wol, g_wol);

    cudaFuncSetAttribute(mm_mma_kernel, cudaFuncAttributeMaxDynamicSharedMemorySize, MM_SMEM);
    cudaFuncSetAttribute(flashmma_kernel, cudaFuncAttributeMaxDynamicSharedMemorySize, FLASH_SMEM);

    dim3 tsb(32, 8);
    // stacked weights: wd = [DKV | DQ | KR], wu = [UK | UV | UQ | QR]
    tsplit_kernel<<<dim3(DCs/32, Dsz/32), tsb>>>(W_DKV, wdh, wdl, Dsz, DCs);
    tsplit_kernel<<<dim3(DCs/32, Dsz/32), tsb>>>(W_DQ,  wdh + (size_t)1024*2048, wdl + (size_t)1024*2048, Dsz, DCs);
    tsplit_kernel<<<dim3(DHRs/32, Dsz/32), tsb>>>(W_KR, wdh + (size_t)2048*2048, wdl + (size_t)2048*2048, Dsz, DHRs);
    tsplit_kernel<<<dim3(Dsz/32, DCs/32), tsb>>>(W_UK,  wuh, wul, DCs, Dsz);
    tsplit_kernel<<<dim3(Dsz/32, DCs/32), tsb>>>(W_UV,  wuh + (size_t)2048*1024, wul + (size_t)2048*1024, DCs, Dsz);
    tsplit_kernel<<<dim3(Dsz/32, DCs/32), tsb>>>(W_UQ,  wuh + (size_t)4096*1024, wul + (size_t)4096*1024, DCs, Dsz);
    tsplit_kernel<<<dim3((NHs*DHRs)/32, DCs/32), tsb>>>(W_QR, wuh + (size_t)6144*1024, wul + (size_t)6144*1024, DCs, NHs*DHRs);
    tsplit_kernel<<<dim3(Dsz/32, Dsz/32), tsb>>>(W_O,   woh, wol, Dsz, Dsz);

    { int n = Msz * Dsz; split_kernel<<<(n / 4 + 255) / 256, 256>>>(x, xh, xl, n); }

    // fused down-projection: N=2176 -> bf16 ckvq (cols<2048) + fp32 kr2 (cols>=2048)
    mm_mma_kernel<<<dim3(2176/128, Msz/256), 256, MM_SMEM>>>(
        xh, xl, xh, xl, 1 << 30, Dsz,
        wdh, wdl, nullptr, kr2, nullptr, nullptr, cvh, cvl, 2176, Dsz);

    // fused up-projection: N=7168; A = c_kv part (n<4096) or c_q part (n>=4096)
    mm_mma_kernel<<<dim3(7168/128, Msz/256), 256, MM_SMEM>>>(
        cvh, cvl, cvh + 1024, cvl + 1024, 4096, 2048,
        wuh, wul, kc, vt, qc, qr, nullptr, nullptr, 7168, DCs);

    // RoPE + concat + normalize -> bf16 hi/lo Q,K,V
    assemble_kernel<<<Msz, 512>>>(s_qk);

    // tensor-core causal flash attention -> aoh/aol
    flashmma_kernel<<<dim3(Lsz / FQ, NHs, Bsz), 256, FLASH_SMEM>>>();

    // output projection
    mm_mma_kernel<<<dim3(Dsz/128, Msz/256), 256, MM_SMEM>>>(
        aoh, aol, aoh, aol, 1 << 30, Dsz,
        woh, wol, out, nullptr, nullptr, nullptr, nullptr, nullptr, Dsz, Dsz);
}